// round 5
// baseline (speedup 1.0000x reference)
#include <cuda_runtime.h>

// Problem constants
#define C_CH   256
#define S_LEN  512
#define D_DIM  256
#define D_IN   256
#define D_FF   1024
#define NROWS  (C_CH * S_LEN)          // 131072 rows of the flattened [C*S, D] view
#define ELEMS  ((long long)NROWS * D_DIM)  // 33,554,432

// ---------------------------------------------------------------------------
// Scratch (static __device__ arrays; allocation inside kernel_launch is banned)
// ---------------------------------------------------------------------------
__device__ float g_x  [NROWS * D_DIM];   // embedded input (residual source)   134 MB
__device__ float g_n  [NROWS * D_DIM];   // layernorm output                   134 MB
__device__ float g_o  [NROWS * D_DIM];   // attention output                   134 MB
__device__ float g_ffn[NROWS * D_FF];    // FFN hidden                         512 MB
__device__ float g_y  [C_CH];            // per-channel pooled mean
__device__ float g_gate[C_CH];           // SE gate

// ---------------------------------------------------------------------------
// Tiled SGEMM: C = alpha * A @ B(^T) [+ bias] [relu], batched via blockIdx.z
//   A: [M,K] row-major. B: NN -> [K,N] row-major; NT -> [N,K] row-major.
//   BM=BN=128, BK=8, 256 threads, 8x8 accumulators per thread.
//   All M,N are multiples of 128 and K multiples of 8 -> no bounds checks.
// ---------------------------------------------------------------------------
template<bool TRANS_B, bool RELU, bool HAS_BIAS>
__global__ __launch_bounds__(256)
void sgemm_kernel(const float* __restrict__ Aall, const float* __restrict__ Ball,
                  const float* __restrict__ bias, float* __restrict__ Call,
                  int M, int N, int K, float alpha,
                  long long sA, long long sB, long long sC)
{
    const float* A = Aall + (long long)blockIdx.z * sA;
    const float* B = Ball + (long long)blockIdx.z * sB;
    float*       Cp = Call + (long long)blockIdx.z * sC;

    __shared__ float As[8][132];   // +4 pad: conflict-free transposed stores,
    __shared__ float Bs[8][132];   // 528B row stride keeps float4 alignment

    const int t  = threadIdx.x;
    const int tx = t & 15;         // 16 x 16 thread grid
    const int ty = t >> 4;

    // A loader: row = by*128 + t/2, 4 k-columns at (t&1)*4  (stored transposed)
    const int aRow = (blockIdx.y << 7) + (t >> 1);
    const int kSub = (t & 1) << 2;
    const float* Aptr = A + (long long)aRow * K + kSub;

    const float* Bptr;
    long long bStep;
    if (TRANS_B) {
        // B[N,K]: row = bx*128 + t/2, 4 k-columns at (t&1)*4 (stored transposed)
        const int bRow = (blockIdx.x << 7) + (t >> 1);
        Bptr  = B + (long long)bRow * K + kSub;
        bStep = 8;
    } else {
        // B[K,N]: row = t/32, 4 n-columns at bx*128 + (t&31)*4 (stored direct)
        const int bRow = t >> 5;
        const int bCol = (blockIdx.x << 7) + ((t & 31) << 2);
        Bptr  = B + (long long)bRow * N + bCol;
        bStep = (long long)8 * N;
    }

    float acc[8][8];
    #pragma unroll
    for (int i = 0; i < 8; i++)
        #pragma unroll
        for (int j = 0; j < 8; j++) acc[i][j] = 0.0f;

    const int m_a = t >> 1;

    for (int k0 = 0; k0 < K; k0 += 8) {
        float4 a = *(const float4*)Aptr;  Aptr += 8;
        As[kSub + 0][m_a] = a.x;
        As[kSub + 1][m_a] = a.y;
        As[kSub + 2][m_a] = a.z;
        As[kSub + 3][m_a] = a.w;

        if (TRANS_B) {
            float4 b = *(const float4*)Bptr;  Bptr += bStep;
            Bs[kSub + 0][m_a] = b.x;
            Bs[kSub + 1][m_a] = b.y;
            Bs[kSub + 2][m_a] = b.z;
            Bs[kSub + 3][m_a] = b.w;
        } else {
            float4 b = *(const float4*)Bptr;  Bptr += bStep;
            *(float4*)&Bs[t >> 5][(t & 31) << 2] = b;
        }
        __syncthreads();

        #pragma unroll
        for (int k = 0; k < 8; k++) {
            float ar[8], br[8];
            *(float4*)&ar[0] = *(const float4*)&As[k][ty << 3];
            *(float4*)&ar[4] = *(const float4*)&As[k][(ty << 3) + 4];
            *(float4*)&br[0] = *(const float4*)&Bs[k][tx << 3];
            *(float4*)&br[4] = *(const float4*)&Bs[k][(tx << 3) + 4];
            #pragma unroll
            for (int i = 0; i < 8; i++)
                #pragma unroll
                for (int j = 0; j < 8; j++)
                    acc[i][j] = fmaf(ar[i], br[j], acc[i][j]);
        }
        __syncthreads();
    }

    // Epilogue
    const int colBase = (blockIdx.x << 7) + (tx << 3);
    float bv[8];
    if (HAS_BIAS) {
        *(float4*)&bv[0] = *(const float4*)&bias[colBase];
        *(float4*)&bv[4] = *(const float4*)&bias[colBase + 4];
    }
    #pragma unroll
    for (int i = 0; i < 8; i++) {
        const long long row = (long long)((blockIdx.y << 7) + (ty << 3) + i);
        float* crow = Cp + row * N + colBase;
        #pragma unroll
        for (int j = 0; j < 8; j += 4) {
            float4 v;
            v.x = acc[i][j + 0] * alpha;
            v.y = acc[i][j + 1] * alpha;
            v.z = acc[i][j + 2] * alpha;
            v.w = acc[i][j + 3] * alpha;
            if (HAS_BIAS) { v.x += bv[j]; v.y += bv[j + 1]; v.z += bv[j + 2]; v.w += bv[j + 3]; }
            if (RELU) {
                v.x = fmaxf(v.x, 0.f); v.y = fmaxf(v.y, 0.f);
                v.z = fmaxf(v.z, 0.f); v.w = fmaxf(v.w, 0.f);
            }
            *(float4*)&crow[j] = v;
        }
    }
}

// ---------------------------------------------------------------------------
// Reductions
// ---------------------------------------------------------------------------
__inline__ __device__ float warpSum(float v) {
    #pragma unroll
    for (int o = 16; o > 0; o >>= 1) v += __shfl_xor_sync(0xffffffffu, v, o);
    return v;
}
__inline__ __device__ float warpMax(float v) {
    #pragma unroll
    for (int o = 16; o > 0; o >>= 1) v = fmaxf(v, __shfl_xor_sync(0xffffffffu, v, o));
    return v;
}

// LayerNorm over D=256; one block (256 threads) per row
__global__ __launch_bounds__(256)
void ln_kernel(const float* __restrict__ x, const float* __restrict__ gamma,
               const float* __restrict__ beta, float* __restrict__ out)
{
    const long long row = blockIdx.x;
    const int t = threadIdx.x;
    const float v = x[row * D_DIM + t];

    __shared__ float sh1[8], sh2[8];
    float s  = warpSum(v);
    float sq = warpSum(v * v);
    const int w = t >> 5, l = t & 31;
    if (l == 0) { sh1[w] = s; sh2[w] = sq; }
    __syncthreads();
    if (w == 0) {
        float a = (l < 8) ? sh1[l] : 0.f;
        float b = (l < 8) ? sh2[l] : 0.f;
        a = warpSum(a); b = warpSum(b);
        if (l == 0) { sh1[0] = a; sh2[0] = b; }
    }
    __syncthreads();
    const float mu  = sh1[0] * (1.0f / D_DIM);
    const float var = sh2[0] * (1.0f / D_DIM) - mu * mu;
    out[row * D_DIM + t] = (v - mu) * rsqrtf(var + 1e-5f) * gamma[t] + beta[t];
}

// Softmax over S=512; one block (256 threads, 2 elems/thread) per row, in-place
__global__ __launch_bounds__(256)
void softmax_kernel(float* __restrict__ p)
{
    const long long row = blockIdx.x;
    float* pr = p + row * S_LEN;
    const int t = threadIdx.x;
    const float a0 = pr[t], a1 = pr[t + 256];

    __shared__ float sh[8];
    const int w = t >> 5, l = t & 31;

    float m = warpMax(fmaxf(a0, a1));
    if (l == 0) sh[w] = m;
    __syncthreads();
    if (w == 0) {
        float v = (l < 8) ? sh[l] : -3.4e38f;
        v = warpMax(v);
        if (l == 0) sh[0] = v;
    }
    __syncthreads();
    const float M = sh[0];
    __syncthreads();

    const float e0 = __expf(a0 - M), e1 = __expf(a1 - M);
    float s = warpSum(e0 + e1);
    if (l == 0) sh[w] = s;
    __syncthreads();
    if (w == 0) {
        float v = (l < 8) ? sh[l] : 0.f;
        v = warpSum(v);
        if (l == 0) sh[0] = v;
    }
    __syncthreads();
    const float inv = 1.0f / sh[0];
    pr[t]       = e0 * inv;
    pr[t + 256] = e1 * inv;
}

// Per-channel mean over S*D = 131072 elements
__global__ __launch_bounds__(256)
void chmean_kernel(const float* __restrict__ h, float* __restrict__ y)
{
    const int c = blockIdx.x;
    const float* hc = h + (long long)c * S_LEN * D_DIM;
    float s = 0.f;
    for (int i = threadIdx.x; i < S_LEN * D_DIM; i += 256) s += hc[i];

    __shared__ float sh[8];
    const int w = threadIdx.x >> 5, l = threadIdx.x & 31;
    s = warpSum(s);
    if (l == 0) sh[w] = s;
    __syncthreads();
    if (w == 0) {
        float v = (l < 8) ? sh[l] : 0.f;
        v = warpSum(v);
        if (l == 0) y[c] = v * (1.0f / (S_LEN * D_DIM));
    }
}

// SE gate: g = sigmoid(relu(y @ W1 + b1) @ W2 + b2); single block
__global__ __launch_bounds__(256)
void se_kernel(const float* __restrict__ y,
               const float* __restrict__ W1, const float* __restrict__ b1,
               const float* __restrict__ W2, const float* __restrict__ b2,
               float* __restrict__ gate)
{
    __shared__ float ys[C_CH];
    __shared__ float hid[16];
    const int t = threadIdx.x;
    ys[t] = y[t];
    __syncthreads();
    if (t < 16) {
        float s = b1[t];
        #pragma unroll 8
        for (int c = 0; c < C_CH; c++) s += ys[c] * W1[c * 16 + t];
        hid[t] = fmaxf(s, 0.f);
    }
    __syncthreads();
    float s = b2[t];
    #pragma unroll
    for (int j = 0; j < 16; j++) s += hid[j] * W2[j * C_CH + t];
    gate[t] = 1.0f / (1.0f + __expf(-s));
}

// out = h * gate[c] + x   (h already sits in `out`)
__global__ __launch_bounds__(256)
void final_kernel(float* __restrict__ out, const float* __restrict__ x,
                  const float* __restrict__ gate)
{
    const long long i = (long long)blockIdx.x * 256 + threadIdx.x;
    const int c = (int)(i >> 17);          // S*D = 131072 = 2^17
    out[i] = out[i] * gate[c] + x[i];
}

// ---------------------------------------------------------------------------
// Launch
// ---------------------------------------------------------------------------
extern "C" void kernel_launch(void* const* d_in, const int* in_sizes, int n_in,
                              void* d_out, int out_size)
{
    const float* input = (const float*)d_in[0];
    const float* W_emb = (const float*)d_in[1];
    const float* b_emb = (const float*)d_in[2];
    const float* ln_g  = (const float*)d_in[3];
    const float* ln_b  = (const float*)d_in[4];
    const float* W1    = (const float*)d_in[5];
    const float* b1    = (const float*)d_in[6];
    const float* W2    = (const float*)d_in[7];
    const float* b2    = (const float*)d_in[8];
    const float* seW1  = (const float*)d_in[9];
    const float* seb1  = (const float*)d_in[10];
    const float* seW2  = (const float*)d_in[11];
    const float* seb2  = (const float*)d_in[12];

    float* out  = (float*)d_out;                  // [C,S,D]  h then final output
    float* attn = out + ELEMS;                    // [C,S,S]  scores then softmax

    float *px, *pn, *po, *pffn, *py, *pg;
    cudaGetSymbolAddress((void**)&px,   g_x);
    cudaGetSymbolAddress((void**)&pn,   g_n);
    cudaGetSymbolAddress((void**)&po,   g_o);
    cudaGetSymbolAddress((void**)&pffn, g_ffn);
    cudaGetSymbolAddress((void**)&py,   g_y);
    cudaGetSymbolAddress((void**)&pg,   g_gate);

    const dim3 blk(256);
    const long long strideN = (long long)S_LEN * D_DIM;   // per-channel n/o stride
    const long long strideP = (long long)S_LEN * S_LEN;   // per-channel attn stride

    // 1) x = input @ W_emb + b_emb             [131072,256] x [256,256]
    sgemm_kernel<false, false, true>
        <<<dim3(D_DIM / 128, NROWS / 128, 1), blk>>>(
            input, W_emb, b_emb, px, NROWS, D_DIM, D_IN, 1.0f, 0, 0, 0);

    // 2) n = LayerNorm(x)
    ln_kernel<<<NROWS, 256>>>(px, ln_g, ln_b, pn);

    // 3) scores = (n @ n^T) / 16   per channel  [512,512]
    sgemm_kernel<true, false, false>
        <<<dim3(S_LEN / 128, S_LEN / 128, C_CH), blk>>>(
            pn, pn, nullptr, attn, S_LEN, S_LEN, D_DIM, 0.0625f,
            strideN, strideN, strideP);

    // 4) attn = softmax(scores) in-place
    softmax_kernel<<<C_CH * S_LEN, 256>>>(attn);

    // 5) o = attn @ n   per channel             [512,512] x [512,256]
    sgemm_kernel<false, false, false>
        <<<dim3(D_DIM / 128, S_LEN / 128, C_CH), blk>>>(
            attn, pn, nullptr, po, S_LEN, D_DIM, S_LEN, 1.0f,
            strideP, strideN, strideN);

    // 6) h1 = relu(o @ W1 + b1)                 [131072,256] x [256,1024]
    sgemm_kernel<false, true, true>
        <<<dim3(D_FF / 128, NROWS / 128, 1), blk>>>(
            po, W1, b1, pffn, NROWS, D_FF, D_DIM, 1.0f, 0, 0, 0);

    // 7) h = h1 @ W2 + b2 -> out region         [131072,1024] x [1024,256]
    sgemm_kernel<false, false, true>
        <<<dim3(D_DIM / 128, NROWS / 128, 1), blk>>>(
            pffn, W2, b2, out, NROWS, D_DIM, D_FF, 1.0f, 0, 0, 0);

    // 8) y[c] = mean(h[c])
    chmean_kernel<<<C_CH, 256>>>(out, py);

    // 9) SE gate
    se_kernel<<<1, 256>>>(py, seW1, seb1, seW2, seb2, pg);

    // 10) out = h * g[c] + x
    final_kernel<<<(unsigned)(ELEMS / 256), 256>>>(out, px, pg);
}

// round 7
// speedup vs baseline: 2.4030x; 2.4030x over previous
#include <cuda_runtime.h>
#include <stdint.h>

// Problem constants
#define C_CH   256
#define S_LEN  512
#define D_DIM  256
#define D_IN   256
#define D_FF   1024
#define NROWS  (C_CH * S_LEN)              // 131072
#define ELEMS  ((long long)NROWS * D_DIM)  // 33,554,432

// ---------------------------------------------------------------------------
// Scratch
// ---------------------------------------------------------------------------
__device__ float g_x  [NROWS * D_DIM];
__device__ float g_n  [NROWS * D_DIM];
__device__ float g_o  [NROWS * D_DIM];
__device__ float g_ffn[NROWS * D_FF];
__device__ float g_y  [C_CH];
__device__ float g_gate[C_CH];

// ---------------------------------------------------------------------------
// tf32 conversion
// ---------------------------------------------------------------------------
__device__ __forceinline__ uint32_t f2tf(float f) {
    uint32_t r;
    asm("cvt.rna.tf32.f32 %0, %1;" : "=r"(r) : "f"(f));
    return r;
}

// ---------------------------------------------------------------------------
// TF32 tensor-core GEMM: C = alpha * A @ B(^T) [+bias] [relu], batch = blockIdx.z
//   A: [M,K] row-major. B: NN -> [K,N]; NT -> [N,K].
//   Tile 128x128x32, 256 threads = 8 warps (2 x 4), 64x32 per warp,
//   16x m16n8k8 tf32 MMA per warp per k-step group.
//   All M,N multiples of 128, K multiples of 32 -> no bounds checks.
// ---------------------------------------------------------------------------
template<bool TRANS_B, bool RELU, bool HAS_BIAS>
__global__ __launch_bounds__(256)
void mma_gemm(const float* __restrict__ Aall, const float* __restrict__ Ball,
              const float* __restrict__ bias, float* __restrict__ Call,
              int M, int N, int K, float alpha,
              long long sA, long long sB, long long sC)
{
    const float* A  = Aall + (long long)blockIdx.z * sA;
    const float* B  = Ball + (long long)blockIdx.z * sB;
    float*       Cp = Call + (long long)blockIdx.z * sC;

    // A[m][k]: stride 36 -> frag banks (4*grp + tig) % 32, conflict-free
    __shared__ uint32_t As[128][36];
    // B[k][n]: stride 136 -> frag banks (8*tig + grp) % 32, conflict-free
    __shared__ uint32_t Bs[32][136];

    const int t     = threadIdx.x;
    const int lane  = t & 31;
    const int warp  = t >> 5;
    const int warpM = warp >> 2;   // 0..1
    const int warpN = warp & 3;    // 0..3
    const int grp   = lane >> 2;
    const int tig   = lane & 3;

    // --- global loaders --------------------------------------------------
    // A: thread t -> row t>>1, k chunks 4*(t&1) + 8*i, i=0..3 (float4 each)
    const int aRow = (blockIdx.y << 7) + (t >> 1);
    const int kSub = (t & 1) << 2;
    const float* aPtr = A + (size_t)aRow * K + kSub;

    const float* bPtr;
    if (TRANS_B) {
        // B[N,K]: row = bx*128 + t>>1, same k-chunk pattern as A
        const int bRow = (blockIdx.x << 7) + (t >> 1);
        bPtr = B + (size_t)bRow * K + kSub;
    } else {
        // B[K,N]: row k = t>>3, n chunks 4*(t&7) + 32*i (columns, same k-row)
        const int bRow = t >> 3;
        const int bCol = (blockIdx.x << 7) + ((t & 7) << 2);
        bPtr = B + (size_t)bRow * N + bCol;
    }

    float acc[4][4][4];
    #pragma unroll
    for (int i = 0; i < 4; i++)
        #pragma unroll
        for (int j = 0; j < 4; j++)
            #pragma unroll
            for (int r = 0; r < 4; r++) acc[i][j][r] = 0.0f;

    float4 pa[4], pb[4];

    // prologue: load k0 = 0
    #pragma unroll
    for (int i = 0; i < 4; i++) pa[i] = *(const float4*)(aPtr + (i << 3));
    #pragma unroll
    for (int i = 0; i < 4; i++)
        pb[i] = TRANS_B ? *(const float4*)(bPtr + (i << 3))
                        : *(const float4*)(bPtr + (i << 5));   // FIX: column offset, not *N

    // ---- store helpers (inline) ----
    auto storeA = [&]() {
        #pragma unroll
        for (int i = 0; i < 4; i++) {
            uint4 v = make_uint4(f2tf(pa[i].x), f2tf(pa[i].y),
                                 f2tf(pa[i].z), f2tf(pa[i].w));
            *(uint4*)&As[t >> 1][kSub + (i << 3)] = v;
        }
    };
    auto storeB = [&]() {
        if (TRANS_B) {
            #pragma unroll
            for (int i = 0; i < 4; i++) {
                const int kk = kSub + (i << 3);
                const int nn = t >> 1;
                Bs[kk + 0][nn] = f2tf(pb[i].x);
                Bs[kk + 1][nn] = f2tf(pb[i].y);
                Bs[kk + 2][nn] = f2tf(pb[i].z);
                Bs[kk + 3][nn] = f2tf(pb[i].w);
            }
        } else {
            #pragma unroll
            for (int i = 0; i < 4; i++) {
                uint4 v = make_uint4(f2tf(pb[i].x), f2tf(pb[i].y),
                                     f2tf(pb[i].z), f2tf(pb[i].w));
                *(uint4*)&Bs[t >> 3][((t & 7) << 2) + (i << 5)] = v;
            }
        }
    };

    storeA(); storeB();
    __syncthreads();

    for (int k0 = 0; k0 < K; k0 += 32) {
        const bool notLast = (k0 + 32 < K);
        if (notLast) {
            const float* ap = aPtr + k0 + 32;
            #pragma unroll
            for (int i = 0; i < 4; i++) pa[i] = *(const float4*)(ap + (i << 3));
            if (TRANS_B) {
                const float* bp = bPtr + k0 + 32;
                #pragma unroll
                for (int i = 0; i < 4; i++) pb[i] = *(const float4*)(bp + (i << 3));
            } else {
                const float* bp = bPtr + (size_t)(k0 + 32) * N;   // advance 32 k-rows
                #pragma unroll
                for (int i = 0; i < 4; i++) pb[i] = *(const float4*)(bp + (i << 5));  // FIX
            }
        }

        // ---- compute on smem tile ----
        #pragma unroll
        for (int ks = 0; ks < 4; ks++) {
            const int k8 = ks << 3;
            uint32_t af[4][4], bf[4][2];
            #pragma unroll
            for (int mt = 0; mt < 4; mt++) {
                const int m0 = (warpM << 6) + (mt << 4) + grp;
                af[mt][0] = As[m0    ][k8 + tig];
                af[mt][1] = As[m0 + 8][k8 + tig];
                af[mt][2] = As[m0    ][k8 + tig + 4];
                af[mt][3] = As[m0 + 8][k8 + tig + 4];
            }
            #pragma unroll
            for (int nt = 0; nt < 4; nt++) {
                const int n0 = (warpN << 5) + (nt << 3) + grp;
                bf[nt][0] = Bs[k8 + tig    ][n0];
                bf[nt][1] = Bs[k8 + tig + 4][n0];
            }
            #pragma unroll
            for (int mt = 0; mt < 4; mt++)
                #pragma unroll
                for (int nt = 0; nt < 4; nt++)
                    asm volatile(
                        "mma.sync.aligned.m16n8k8.row.col.f32.tf32.tf32.f32 "
                        "{%0,%1,%2,%3}, {%4,%5,%6,%7}, {%8,%9}, {%0,%1,%2,%3};"
                        : "+f"(acc[mt][nt][0]), "+f"(acc[mt][nt][1]),
                          "+f"(acc[mt][nt][2]), "+f"(acc[mt][nt][3])
                        : "r"(af[mt][0]), "r"(af[mt][1]),
                          "r"(af[mt][2]), "r"(af[mt][3]),
                          "r"(bf[nt][0]), "r"(bf[nt][1]));
        }
        __syncthreads();

        if (notLast) {
            storeA(); storeB();
            __syncthreads();
        }
    }

    // ---- epilogue ----
    const int rowB = (blockIdx.y << 7) + (warpM << 6) + grp;
    const int colB = (blockIdx.x << 7) + (warpN << 5) + (tig << 1);

    #pragma unroll
    for (int nt = 0; nt < 4; nt++) {
        const int col = colB + (nt << 3);
        float b0 = 0.f, b1 = 0.f;
        if (HAS_BIAS) { b0 = bias[col]; b1 = bias[col + 1]; }
        #pragma unroll
        for (int mt = 0; mt < 4; mt++) {
            float v0 = acc[mt][nt][0] * alpha + b0;
            float v1 = acc[mt][nt][1] * alpha + b1;
            float v2 = acc[mt][nt][2] * alpha + b0;
            float v3 = acc[mt][nt][3] * alpha + b1;
            if (RELU) {
                v0 = fmaxf(v0, 0.f); v1 = fmaxf(v1, 0.f);
                v2 = fmaxf(v2, 0.f); v3 = fmaxf(v3, 0.f);
            }
            const int r0 = rowB + (mt << 4);
            *(float2*)(Cp + (size_t)r0 * N + col)       = make_float2(v0, v1);
            *(float2*)(Cp + (size_t)(r0 + 8) * N + col) = make_float2(v2, v3);
        }
    }
}

// ---------------------------------------------------------------------------
// Reductions
// ---------------------------------------------------------------------------
__inline__ __device__ float warpSum(float v) {
    #pragma unroll
    for (int o = 16; o > 0; o >>= 1) v += __shfl_xor_sync(0xffffffffu, v, o);
    return v;
}
__inline__ __device__ float warpMax(float v) {
    #pragma unroll
    for (int o = 16; o > 0; o >>= 1) v = fmaxf(v, __shfl_xor_sync(0xffffffffu, v, o));
    return v;
}

// LayerNorm over D=256; one block (256 threads) per row
__global__ __launch_bounds__(256)
void ln_kernel(const float* __restrict__ x, const float* __restrict__ gamma,
               const float* __restrict__ beta, float* __restrict__ out)
{
    const long long row = blockIdx.x;
    const int t = threadIdx.x;
    const float v = x[row * D_DIM + t];

    __shared__ float sh1[8], sh2[8];
    float s  = warpSum(v);
    float sq = warpSum(v * v);
    const int w = t >> 5, l = t & 31;
    if (l == 0) { sh1[w] = s; sh2[w] = sq; }
    __syncthreads();
    if (w == 0) {
        float a = (l < 8) ? sh1[l] : 0.f;
        float b = (l < 8) ? sh2[l] : 0.f;
        a = warpSum(a); b = warpSum(b);
        if (l == 0) { sh1[0] = a; sh2[0] = b; }
    }
    __syncthreads();
    const float mu  = sh1[0] * (1.0f / D_DIM);
    const float var = sh2[0] * (1.0f / D_DIM) - mu * mu;
    out[row * D_DIM + t] = (v - mu) * rsqrtf(var + 1e-5f) * gamma[t] + beta[t];
}

// Softmax over S=512; one block (128 threads, float4 each) per row, in-place
__global__ __launch_bounds__(128)
void softmax_kernel(float* __restrict__ p)
{
    const long long row = blockIdx.x;
    float* pr = p + row * S_LEN;
    const int t = threadIdx.x;
    const int w = t >> 5, l = t & 31;

    float4 a = *(float4*)(pr + (t << 2));
    __shared__ float sh[4], sh2[4];

    float m = fmaxf(fmaxf(a.x, a.y), fmaxf(a.z, a.w));
    m = warpMax(m);
    if (l == 0) sh[w] = m;
    __syncthreads();
    m = fmaxf(fmaxf(sh[0], sh[1]), fmaxf(sh[2], sh[3]));

    a.x = __expf(a.x - m); a.y = __expf(a.y - m);
    a.z = __expf(a.z - m); a.w = __expf(a.w - m);
    float s = warpSum(a.x + a.y + a.z + a.w);
    if (l == 0) sh2[w] = s;
    __syncthreads();
    const float inv = 1.0f / (sh2[0] + sh2[1] + sh2[2] + sh2[3]);

    a.x *= inv; a.y *= inv; a.z *= inv; a.w *= inv;
    *(float4*)(pr + (t << 2)) = a;
}

// Per-channel mean over S*D = 131072 elements (float4)
__global__ __launch_bounds__(256)
void chmean_kernel(const float* __restrict__ h, float* __restrict__ y)
{
    const int c = blockIdx.x;
    const float4* hc = (const float4*)(h + (long long)c * S_LEN * D_DIM);
    float s = 0.f;
    for (int i = threadIdx.x; i < S_LEN * D_DIM / 4; i += 256) {
        float4 v = hc[i];
        s += (v.x + v.y) + (v.z + v.w);
    }
    __shared__ float sh[8];
    const int w = threadIdx.x >> 5, l = threadIdx.x & 31;
    s = warpSum(s);
    if (l == 0) sh[w] = s;
    __syncthreads();
    if (w == 0) {
        float v = (l < 8) ? sh[l] : 0.f;
        v = warpSum(v);
        if (l == 0) y[c] = v * (1.0f / (S_LEN * D_DIM));
    }
}

// SE gate: g = sigmoid(relu(y @ W1 + b1) @ W2 + b2); single block
__global__ __launch_bounds__(256)
void se_kernel(const float* __restrict__ y,
               const float* __restrict__ W1, const float* __restrict__ b1,
               const float* __restrict__ W2, const float* __restrict__ b2,
               float* __restrict__ gate)
{
    __shared__ float ys[C_CH];
    __shared__ float hid[16];
    const int t = threadIdx.x;
    ys[t] = y[t];
    __syncthreads();
    if (t < 16) {
        float s = b1[t];
        #pragma unroll 8
        for (int c = 0; c < C_CH; c++) s += ys[c] * W1[c * 16 + t];
        hid[t] = fmaxf(s, 0.f);
    }
    __syncthreads();
    float s = b2[t];
    #pragma unroll
    for (int j = 0; j < 16; j++) s += hid[j] * W2[j * C_CH + t];
    gate[t] = 1.0f / (1.0f + __expf(-s));
}

// out = h * gate[c] + x   (h already in `out`), float4
__global__ __launch_bounds__(256)
void final_kernel(float* __restrict__ out, const float* __restrict__ x,
                  const float* __restrict__ gate)
{
    const long long i4 = (long long)blockIdx.x * 256 + threadIdx.x;
    const int c = (int)(i4 >> 15);        // (i4*4) >> 17
    const float g = gate[c];
    float4 h = ((float4*)out)[i4];
    float4 xv = ((const float4*)x)[i4];
    h.x = h.x * g + xv.x;
    h.y = h.y * g + xv.y;
    h.z = h.z * g + xv.z;
    h.w = h.w * g + xv.w;
    ((float4*)out)[i4] = h;
}

// ---------------------------------------------------------------------------
// Launch
// ---------------------------------------------------------------------------
extern "C" void kernel_launch(void* const* d_in, const int* in_sizes, int n_in,
                              void* d_out, int out_size)
{
    const float* input = (const float*)d_in[0];
    const float* W_emb = (const float*)d_in[1];
    const float* b_emb = (const float*)d_in[2];
    const float* ln_g  = (const float*)d_in[3];
    const float* ln_b  = (const float*)d_in[4];
    const float* W1    = (const float*)d_in[5];
    const float* b1    = (const float*)d_in[6];
    const float* W2    = (const float*)d_in[7];
    const float* b2    = (const float*)d_in[8];
    const float* seW1  = (const float*)d_in[9];
    const float* seb1  = (const float*)d_in[10];
    const float* seW2  = (const float*)d_in[11];
    const float* seb2  = (const float*)d_in[12];

    float* out  = (float*)d_out;               // [C,S,D]
    float* attn = out + ELEMS;                 // [C,S,S]

    float *px, *pn, *po, *pffn, *py, *pg;
    cudaGetSymbolAddress((void**)&px,   g_x);
    cudaGetSymbolAddress((void**)&pn,   g_n);
    cudaGetSymbolAddress((void**)&po,   g_o);
    cudaGetSymbolAddress((void**)&pffn, g_ffn);
    cudaGetSymbolAddress((void**)&py,   g_y);
    cudaGetSymbolAddress((void**)&pg,   g_gate);

    const dim3 blk(256);
    const long long strideN = (long long)S_LEN * D_DIM;
    const long long strideP = (long long)S_LEN * S_LEN;

    // 1) x = input @ W_emb + b_emb             [131072,256] x [256,256]
    mma_gemm<false, false, true>
        <<<dim3(D_DIM / 128, NROWS / 128, 1), blk>>>(
            input, W_emb, b_emb, px, NROWS, D_DIM, D_IN, 1.0f, 0, 0, 0);

    // 2) n = LayerNorm(x)
    ln_kernel<<<NROWS, 256>>>(px, ln_g, ln_b, pn);

    // 3) scores = (n @ n^T) / 16   per channel  [512,512]
    mma_gemm<true, false, false>
        <<<dim3(S_LEN / 128, S_LEN / 128, C_CH), blk>>>(
            pn, pn, nullptr, attn, S_LEN, S_LEN, D_DIM, 0.0625f,
            strideN, strideN, strideP);

    // 4) attn = softmax(scores) in-place
    softmax_kernel<<<C_CH * S_LEN, 128>>>(attn);

    // 5) o = attn @ n   per channel             [512,512] x [512,256]
    mma_gemm<false, false, false>
        <<<dim3(D_DIM / 128, S_LEN / 128, C_CH), blk>>>(
            attn, pn, nullptr, po, S_LEN, D_DIM, S_LEN, 1.0f,
            strideP, strideN, strideN);

    // 6) h1 = relu(o @ W1 + b1)                 [131072,256] x [256,1024]
    mma_gemm<false, true, true>
        <<<dim3(D_FF / 128, NROWS / 128, 1), blk>>>(
            po, W1, b1, pffn, NROWS, D_FF, D_DIM, 1.0f, 0, 0, 0);

    // 7) h = h1 @ W2 + b2 -> out region         [131072,1024] x [1024,256]
    mma_gemm<false, false, true>
        <<<dim3(D_DIM / 128, NROWS / 128, 1), blk>>>(
            pffn, W2, b2, out, NROWS, D_DIM, D_FF, 1.0f, 0, 0, 0);

    // 8) y[c] = mean(h[c])
    chmean_kernel<<<C_CH, 256>>>(out, py);

    // 9) SE gate
    se_kernel<<<1, 256>>>(py, seW1, seb1, seW2, seb2, pg);

    // 10) out = h * g[c] + x
    final_kernel<<<(unsigned)(ELEMS / 1024), 256>>>(out, px, pg);
}

// round 8
// speedup vs baseline: 2.4079x; 1.0020x over previous
#include <cuda_runtime.h>
#include <stdint.h>

// Problem constants
#define C_CH   256
#define S_LEN  512
#define D_DIM  256
#define D_IN   256
#define D_FF   1024
#define NROWS  (C_CH * S_LEN)              // 131072
#define ELEMS  ((long long)NROWS * D_DIM)  // 33,554,432

// ---------------------------------------------------------------------------
// Scratch
// ---------------------------------------------------------------------------
__device__ float g_x  [NROWS * D_DIM];
__device__ float g_n  [NROWS * D_DIM];
__device__ float g_o  [NROWS * D_DIM];
__device__ float g_ffn[NROWS * D_FF];
__device__ float g_y  [C_CH];
__device__ float g_gate[C_CH];

// ---------------------------------------------------------------------------
// tf32 conversion
// ---------------------------------------------------------------------------
__device__ __forceinline__ uint32_t f2tf(float f) {
    uint32_t r;
    asm("cvt.rna.tf32.f32 %0, %1;" : "=r"(r) : "f"(f));
    return r;
}

// ---------------------------------------------------------------------------
// TF32 tensor-core GEMM: C = alpha * A @ B(^T) [+bias] [relu], batch = blockIdx.z
//   A: [M,K] row-major. B: NN -> [K,N]; NT -> [N,K].
//   Tile 128x128x32, 256 threads = 8 warps (2 x 4), 64x32 per warp,
//   16x m16n8k8 tf32 MMA per warp per k-step group.
//   All M,N multiples of 128, K multiples of 32 -> no bounds checks.
// ---------------------------------------------------------------------------
template<bool TRANS_B, bool RELU, bool HAS_BIAS>
__global__ __launch_bounds__(256)
void mma_gemm(const float* __restrict__ Aall, const float* __restrict__ Ball,
              const float* __restrict__ bias, float* __restrict__ Call,
              int M, int N, int K, float alpha,
              long long sA, long long sB, long long sC)
{
    const float* A  = Aall + (long long)blockIdx.z * sA;
    const float* B  = Ball + (long long)blockIdx.z * sB;
    float*       Cp = Call + (long long)blockIdx.z * sC;

    // A[m][k]: stride 36 -> frag banks (4*grp + tig) % 32, conflict-free
    __shared__ uint32_t As[128][36];
    // B[k][n]: stride 136 -> frag banks (8*tig + grp) % 32, conflict-free
    __shared__ uint32_t Bs[32][136];

    const int t     = threadIdx.x;
    const int lane  = t & 31;
    const int warp  = t >> 5;
    const int warpM = warp >> 2;   // 0..1
    const int warpN = warp & 3;    // 0..3
    const int grp   = lane >> 2;
    const int tig   = lane & 3;

    // --- global loaders --------------------------------------------------
    // A: thread t -> row t>>1, k chunks 4*(t&1) + 8*i, i=0..3 (float4 each)
    const int aRow = (blockIdx.y << 7) + (t >> 1);
    const int kSub = (t & 1) << 2;
    const float* aPtr = A + (size_t)aRow * K + kSub;

    const float* bPtr;
    if (TRANS_B) {
        // B[N,K]: row = bx*128 + t>>1, same k-chunk pattern as A
        const int bRow = (blockIdx.x << 7) + (t >> 1);
        bPtr = B + (size_t)bRow * K + kSub;
    } else {
        // B[K,N]: row k = t>>3, n chunks 4*(t&7) + 32*i (columns, same k-row)
        const int bRow = t >> 3;
        const int bCol = (blockIdx.x << 7) + ((t & 7) << 2);
        bPtr = B + (size_t)bRow * N + bCol;
    }

    float acc[4][4][4];
    #pragma unroll
    for (int i = 0; i < 4; i++)
        #pragma unroll
        for (int j = 0; j < 4; j++)
            #pragma unroll
            for (int r = 0; r < 4; r++) acc[i][j][r] = 0.0f;

    float4 pa[4], pb[4];

    // prologue: load k0 = 0
    #pragma unroll
    for (int i = 0; i < 4; i++) pa[i] = *(const float4*)(aPtr + (i << 3));
    #pragma unroll
    for (int i = 0; i < 4; i++)
        pb[i] = TRANS_B ? *(const float4*)(bPtr + (i << 3))
                        : *(const float4*)(bPtr + (i << 5));   // FIX: column offset, not *N

    // ---- store helpers (inline) ----
    auto storeA = [&]() {
        #pragma unroll
        for (int i = 0; i < 4; i++) {
            uint4 v = make_uint4(f2tf(pa[i].x), f2tf(pa[i].y),
                                 f2tf(pa[i].z), f2tf(pa[i].w));
            *(uint4*)&As[t >> 1][kSub + (i << 3)] = v;
        }
    };
    auto storeB = [&]() {
        if (TRANS_B) {
            #pragma unroll
            for (int i = 0; i < 4; i++) {
                const int kk = kSub + (i << 3);
                const int nn = t >> 1;
                Bs[kk + 0][nn] = f2tf(pb[i].x);
                Bs[kk + 1][nn] = f2tf(pb[i].y);
                Bs[kk + 2][nn] = f2tf(pb[i].z);
                Bs[kk + 3][nn] = f2tf(pb[i].w);
            }
        } else {
            #pragma unroll
            for (int i = 0; i < 4; i++) {
                uint4 v = make_uint4(f2tf(pb[i].x), f2tf(pb[i].y),
                                     f2tf(pb[i].z), f2tf(pb[i].w));
                *(uint4*)&Bs[t >> 3][((t & 7) << 2) + (i << 5)] = v;
            }
        }
    };

    storeA(); storeB();
    __syncthreads();

    for (int k0 = 0; k0 < K; k0 += 32) {
        const bool notLast = (k0 + 32 < K);
        if (notLast) {
            const float* ap = aPtr + k0 + 32;
            #pragma unroll
            for (int i = 0; i < 4; i++) pa[i] = *(const float4*)(ap + (i << 3));
            if (TRANS_B) {
                const float* bp = bPtr + k0 + 32;
                #pragma unroll
                for (int i = 0; i < 4; i++) pb[i] = *(const float4*)(bp + (i << 3));
            } else {
                const float* bp = bPtr + (size_t)(k0 + 32) * N;   // advance 32 k-rows
                #pragma unroll
                for (int i = 0; i < 4; i++) pb[i] = *(const float4*)(bp + (i << 5));  // FIX
            }
        }

        // ---- compute on smem tile ----
        #pragma unroll
        for (int ks = 0; ks < 4; ks++) {
            const int k8 = ks << 3;
            uint32_t af[4][4], bf[4][2];
            #pragma unroll
            for (int mt = 0; mt < 4; mt++) {
                const int m0 = (warpM << 6) + (mt << 4) + grp;
                af[mt][0] = As[m0    ][k8 + tig];
                af[mt][1] = As[m0 + 8][k8 + tig];
                af[mt][2] = As[m0    ][k8 + tig + 4];
                af[mt][3] = As[m0 + 8][k8 + tig + 4];
            }
            #pragma unroll
            for (int nt = 0; nt < 4; nt++) {
                const int n0 = (warpN << 5) + (nt << 3) + grp;
                bf[nt][0] = Bs[k8 + tig    ][n0];
                bf[nt][1] = Bs[k8 + tig + 4][n0];
            }
            #pragma unroll
            for (int mt = 0; mt < 4; mt++)
                #pragma unroll
                for (int nt = 0; nt < 4; nt++)
                    asm volatile(
                        "mma.sync.aligned.m16n8k8.row.col.f32.tf32.tf32.f32 "
                        "{%0,%1,%2,%3}, {%4,%5,%6,%7}, {%8,%9}, {%0,%1,%2,%3};"
                        : "+f"(acc[mt][nt][0]), "+f"(acc[mt][nt][1]),
                          "+f"(acc[mt][nt][2]), "+f"(acc[mt][nt][3])
                        : "r"(af[mt][0]), "r"(af[mt][1]),
                          "r"(af[mt][2]), "r"(af[mt][3]),
                          "r"(bf[nt][0]), "r"(bf[nt][1]));
        }
        __syncthreads();

        if (notLast) {
            storeA(); storeB();
            __syncthreads();
        }
    }

    // ---- epilogue ----
    const int rowB = (blockIdx.y << 7) + (warpM << 6) + grp;
    const int colB = (blockIdx.x << 7) + (warpN << 5) + (tig << 1);

    #pragma unroll
    for (int nt = 0; nt < 4; nt++) {
        const int col = colB + (nt << 3);
        float b0 = 0.f, b1 = 0.f;
        if (HAS_BIAS) { b0 = bias[col]; b1 = bias[col + 1]; }
        #pragma unroll
        for (int mt = 0; mt < 4; mt++) {
            float v0 = acc[mt][nt][0] * alpha + b0;
            float v1 = acc[mt][nt][1] * alpha + b1;
            float v2 = acc[mt][nt][2] * alpha + b0;
            float v3 = acc[mt][nt][3] * alpha + b1;
            if (RELU) {
                v0 = fmaxf(v0, 0.f); v1 = fmaxf(v1, 0.f);
                v2 = fmaxf(v2, 0.f); v3 = fmaxf(v3, 0.f);
            }
            const int r0 = rowB + (mt << 4);
            *(float2*)(Cp + (size_t)r0 * N + col)       = make_float2(v0, v1);
            *(float2*)(Cp + (size_t)(r0 + 8) * N + col) = make_float2(v2, v3);
        }
    }
}

// ---------------------------------------------------------------------------
// Reductions
// ---------------------------------------------------------------------------
__inline__ __device__ float warpSum(float v) {
    #pragma unroll
    for (int o = 16; o > 0; o >>= 1) v += __shfl_xor_sync(0xffffffffu, v, o);
    return v;
}
__inline__ __device__ float warpMax(float v) {
    #pragma unroll
    for (int o = 16; o > 0; o >>= 1) v = fmaxf(v, __shfl_xor_sync(0xffffffffu, v, o));
    return v;
}

// LayerNorm over D=256; one block (256 threads) per row
__global__ __launch_bounds__(256)
void ln_kernel(const float* __restrict__ x, const float* __restrict__ gamma,
               const float* __restrict__ beta, float* __restrict__ out)
{
    const long long row = blockIdx.x;
    const int t = threadIdx.x;
    const float v = x[row * D_DIM + t];

    __shared__ float sh1[8], sh2[8];
    float s  = warpSum(v);
    float sq = warpSum(v * v);
    const int w = t >> 5, l = t & 31;
    if (l == 0) { sh1[w] = s; sh2[w] = sq; }
    __syncthreads();
    if (w == 0) {
        float a = (l < 8) ? sh1[l] : 0.f;
        float b = (l < 8) ? sh2[l] : 0.f;
        a = warpSum(a); b = warpSum(b);
        if (l == 0) { sh1[0] = a; sh2[0] = b; }
    }
    __syncthreads();
    const float mu  = sh1[0] * (1.0f / D_DIM);
    const float var = sh2[0] * (1.0f / D_DIM) - mu * mu;
    out[row * D_DIM + t] = (v - mu) * rsqrtf(var + 1e-5f) * gamma[t] + beta[t];
}

// Softmax over S=512; one block (128 threads, float4 each) per row, in-place
__global__ __launch_bounds__(128)
void softmax_kernel(float* __restrict__ p)
{
    const long long row = blockIdx.x;
    float* pr = p + row * S_LEN;
    const int t = threadIdx.x;
    const int w = t >> 5, l = t & 31;

    float4 a = *(float4*)(pr + (t << 2));
    __shared__ float sh[4], sh2[4];

    float m = fmaxf(fmaxf(a.x, a.y), fmaxf(a.z, a.w));
    m = warpMax(m);
    if (l == 0) sh[w] = m;
    __syncthreads();
    m = fmaxf(fmaxf(sh[0], sh[1]), fmaxf(sh[2], sh[3]));

    a.x = __expf(a.x - m); a.y = __expf(a.y - m);
    a.z = __expf(a.z - m); a.w = __expf(a.w - m);
    float s = warpSum(a.x + a.y + a.z + a.w);
    if (l == 0) sh2[w] = s;
    __syncthreads();
    const float inv = 1.0f / (sh2[0] + sh2[1] + sh2[2] + sh2[3]);

    a.x *= inv; a.y *= inv; a.z *= inv; a.w *= inv;
    *(float4*)(pr + (t << 2)) = a;
}

// Per-channel mean over S*D = 131072 elements (float4)
__global__ __launch_bounds__(256)
void chmean_kernel(const float* __restrict__ h, float* __restrict__ y)
{
    const int c = blockIdx.x;
    const float4* hc = (const float4*)(h + (long long)c * S_LEN * D_DIM);
    float s = 0.f;
    for (int i = threadIdx.x; i < S_LEN * D_DIM / 4; i += 256) {
        float4 v = hc[i];
        s += (v.x + v.y) + (v.z + v.w);
    }
    __shared__ float sh[8];
    const int w = threadIdx.x >> 5, l = threadIdx.x & 31;
    s = warpSum(s);
    if (l == 0) sh[w] = s;
    __syncthreads();
    if (w == 0) {
        float v = (l < 8) ? sh[l] : 0.f;
        v = warpSum(v);
        if (l == 0) y[c] = v * (1.0f / (S_LEN * D_DIM));
    }
}

// SE gate: g = sigmoid(relu(y @ W1 + b1) @ W2 + b2); single block
__global__ __launch_bounds__(256)
void se_kernel(const float* __restrict__ y,
               const float* __restrict__ W1, const float* __restrict__ b1,
               const float* __restrict__ W2, const float* __restrict__ b2,
               float* __restrict__ gate)
{
    __shared__ float ys[C_CH];
    __shared__ float hid[16];
    const int t = threadIdx.x;
    ys[t] = y[t];
    __syncthreads();
    if (t < 16) {
        float s = b1[t];
        #pragma unroll 8
        for (int c = 0; c < C_CH; c++) s += ys[c] * W1[c * 16 + t];
        hid[t] = fmaxf(s, 0.f);
    }
    __syncthreads();
    float s = b2[t];
    #pragma unroll
    for (int j = 0; j < 16; j++) s += hid[j] * W2[j * C_CH + t];
    gate[t] = 1.0f / (1.0f + __expf(-s));
}

// out = h * gate[c] + x   (h already in `out`), float4
__global__ __launch_bounds__(256)
void final_kernel(float* __restrict__ out, const float* __restrict__ x,
                  const float* __restrict__ gate)
{
    const long long i4 = (long long)blockIdx.x * 256 + threadIdx.x;
    const int c = (int)(i4 >> 15);        // (i4*4) >> 17
    const float g = gate[c];
    float4 h = ((float4*)out)[i4];
    float4 xv = ((const float4*)x)[i4];
    h.x = h.x * g + xv.x;
    h.y = h.y * g + xv.y;
    h.z = h.z * g + xv.z;
    h.w = h.w * g + xv.w;
    ((float4*)out)[i4] = h;
}

// ---------------------------------------------------------------------------
// Launch
// ---------------------------------------------------------------------------
extern "C" void kernel_launch(void* const* d_in, const int* in_sizes, int n_in,
                              void* d_out, int out_size)
{
    const float* input = (const float*)d_in[0];
    const float* W_emb = (const float*)d_in[1];
    const float* b_emb = (const float*)d_in[2];
    const float* ln_g  = (const float*)d_in[3];
    const float* ln_b  = (const float*)d_in[4];
    const float* W1    = (const float*)d_in[5];
    const float* b1    = (const float*)d_in[6];
    const float* W2    = (const float*)d_in[7];
    const float* b2    = (const float*)d_in[8];
    const float* seW1  = (const float*)d_in[9];
    const float* seb1  = (const float*)d_in[10];
    const float* seW2  = (const float*)d_in[11];
    const float* seb2  = (const float*)d_in[12];

    float* out  = (float*)d_out;               // [C,S,D]
    float* attn = out + ELEMS;                 // [C,S,S]

    float *px, *pn, *po, *pffn, *py, *pg;
    cudaGetSymbolAddress((void**)&px,   g_x);
    cudaGetSymbolAddress((void**)&pn,   g_n);
    cudaGetSymbolAddress((void**)&po,   g_o);
    cudaGetSymbolAddress((void**)&pffn, g_ffn);
    cudaGetSymbolAddress((void**)&py,   g_y);
    cudaGetSymbolAddress((void**)&pg,   g_gate);

    const dim3 blk(256);
    const long long strideN = (long long)S_LEN * D_DIM;
    const long long strideP = (long long)S_LEN * S_LEN;

    // 1) x = input @ W_emb + b_emb             [131072,256] x [256,256]
    mma_gemm<false, false, true>
        <<<dim3(D_DIM / 128, NROWS / 128, 1), blk>>>(
            input, W_emb, b_emb, px, NROWS, D_DIM, D_IN, 1.0f, 0, 0, 0);

    // 2) n = LayerNorm(x)
    ln_kernel<<<NROWS, 256>>>(px, ln_g, ln_b, pn);

    // 3) scores = (n @ n^T) / 16   per channel  [512,512]
    mma_gemm<true, false, false>
        <<<dim3(S_LEN / 128, S_LEN / 128, C_CH), blk>>>(
            pn, pn, nullptr, attn, S_LEN, S_LEN, D_DIM, 0.0625f,
            strideN, strideN, strideP);

    // 4) attn = softmax(scores) in-place
    softmax_kernel<<<C_CH * S_LEN, 128>>>(attn);

    // 5) o = attn @ n   per channel             [512,512] x [512,256]
    mma_gemm<false, false, false>
        <<<dim3(D_DIM / 128, S_LEN / 128, C_CH), blk>>>(
            attn, pn, nullptr, po, S_LEN, D_DIM, S_LEN, 1.0f,
            strideP, strideN, strideN);

    // 6) h1 = relu(o @ W1 + b1)                 [131072,256] x [256,1024]
    mma_gemm<false, true, true>
        <<<dim3(D_FF / 128, NROWS / 128, 1), blk>>>(
            po, W1, b1, pffn, NROWS, D_FF, D_DIM, 1.0f, 0, 0, 0);

    // 7) h = h1 @ W2 + b2 -> out region         [131072,1024] x [1024,256]
    mma_gemm<false, false, true>
        <<<dim3(D_DIM / 128, NROWS / 128, 1), blk>>>(
            pffn, W2, b2, out, NROWS, D_DIM, D_FF, 1.0f, 0, 0, 0);

    // 8) y[c] = mean(h[c])
    chmean_kernel<<<C_CH, 256>>>(out, py);

    // 9) SE gate
    se_kernel<<<1, 256>>>(py, seW1, seb1, seW2, seb2, pg);

    // 10) out = h * g[c] + x
    final_kernel<<<(unsigned)(ELEMS / 1024), 256>>>(out, px, pg);
}

// round 9
// speedup vs baseline: 2.9948x; 1.2437x over previous
#include <cuda_runtime.h>
#include <cuda_fp16.h>
#include <stdint.h>

// Problem constants
#define C_CH   256
#define S_LEN  512
#define D_DIM  256
#define D_IN   256
#define D_FF   1024
#define NROWS  (C_CH * S_LEN)              // 131072
#define ELEMS  ((long long)NROWS * D_DIM)  // 33,554,432

// ---------------------------------------------------------------------------
// Scratch
// ---------------------------------------------------------------------------
__device__ float g_x  [NROWS * D_DIM];
__device__ float g_n  [NROWS * D_DIM];
__device__ float g_o  [NROWS * D_DIM];
__device__ float g_ffn[NROWS * D_FF];
__device__ float g_y  [C_CH];
__device__ float g_gate[C_CH];

// pack two floats into half2 (lo = a, hi = b)
__device__ __forceinline__ uint32_t f2h2(float a, float b) {
    __half2 h = __floats2half2_rn(a, b);
    return *(uint32_t*)&h;
}

// ---------------------------------------------------------------------------
// FP16 tensor-core GEMM (fp32 accumulate):
//   C = alpha * A @ B(^T) [+bias] [relu], batch = blockIdx.z
//   A: [M,K] row-major. B: NN -> [K,N]; NT -> [N,K].
//   Tile 128x128x32, 256 threads = 8 warps (2 x 4), 64x32 per warp.
//   mma.sync m16n8k16.f16 with f32 accumulators.
//   M,N multiples of 128; K multiples of 32 -> no bounds checks.
//   Smem holds half2 (uint32 = 2 consecutive K values).
// ---------------------------------------------------------------------------
template<bool TRANS_B, bool RELU, bool HAS_BIAS>
__global__ __launch_bounds__(256)
void mma_gemm(const float* __restrict__ Aall, const float* __restrict__ Ball,
              const float* __restrict__ bias, float* __restrict__ Call,
              int M, int N, int K, float alpha,
              long long sA, long long sB, long long sC)
{
    const float* A  = Aall + (long long)blockIdx.z * sA;
    const float* B  = Ball + (long long)blockIdx.z * sB;
    float*       Cp = Call + (long long)blockIdx.z * sC;

    // A[m][k2]: 16 half2 cols + 4 pad -> frag banks (20*grp + tig)%32 distinct
    __shared__ uint32_t As[128][20];
    // B[k2][n]: 128 cols + 8 pad -> frag banks (8*tig + grp)%32 distinct
    __shared__ uint32_t Bs[16][136];

    const int t     = threadIdx.x;
    const int lane  = t & 31;
    const int warp  = t >> 5;
    const int warpM = warp >> 2;   // 0..1
    const int warpN = warp & 3;    // 0..3
    const int grp   = lane >> 2;
    const int tig   = lane & 3;

    // --- global loaders --------------------------------------------------
    // A: thread t -> row t>>1, float4 at k = 4*(t&1) + 8*i  (i = 0..3)
    const int aRow = (blockIdx.y << 7) + (t >> 1);
    const int kSub = (t & 1) << 2;
    const float* aPtr = A + (size_t)aRow * K + kSub;

    const float* bPtr;
    int kpNN = 0, cbNN = 0;
    if (TRANS_B) {
        // B[N,K]: row n = bx*128 + t>>1, float4 at k = 4*(t&1) + 8*i
        const int bRow = (blockIdx.x << 7) + (t >> 1);
        bPtr = B + (size_t)bRow * K + kSub;
    } else {
        // B[K,N]: thread t -> k-pair kp = t>>4 (rows 2kp, 2kp+1),
        //         8 n-cols at cb = 8*(t&15)
        kpNN = t >> 4;
        cbNN = (t & 15) << 3;
        bPtr = B + (size_t)(kpNN << 1) * N + (blockIdx.x << 7) + cbNN;
    }

    float acc[4][4][4];
    #pragma unroll
    for (int i = 0; i < 4; i++)
        #pragma unroll
        for (int j = 0; j < 4; j++)
            #pragma unroll
            for (int r = 0; r < 4; r++) acc[i][j][r] = 0.0f;

    float4 pa[4], pb[4];

    // ---- global load helpers (offset = k0 of slab) ----
    auto loadA = [&](int k0) {
        const float* ap = aPtr + k0;
        #pragma unroll
        for (int i = 0; i < 4; i++) pa[i] = *(const float4*)(ap + (i << 3));
    };
    auto loadB = [&](int k0) {
        if (TRANS_B) {
            const float* bp = bPtr + k0;
            #pragma unroll
            for (int i = 0; i < 4; i++) pb[i] = *(const float4*)(bp + (i << 3));
        } else {
            const float* bp = bPtr + (size_t)k0 * N;
            pb[0] = *(const float4*)(bp);
            pb[1] = *(const float4*)(bp + 4);
            pb[2] = *(const float4*)(bp + N);
            pb[3] = *(const float4*)(bp + N + 4);
        }
    };

    // ---- smem store helpers ----
    auto storeA = [&]() {
        const int row = t >> 1;
        const int c0  = (t & 1) << 1;          // half2 col base: 0 or 2
        #pragma unroll
        for (int i = 0; i < 4; i++) {
            uint2 v;
            v.x = f2h2(pa[i].x, pa[i].y);
            v.y = f2h2(pa[i].z, pa[i].w);
            *(uint2*)&As[row][c0 + (i << 2)] = v;
        }
    };
    auto storeB = [&]() {
        if (TRANS_B) {
            const int nn = t >> 1;
            const int c0 = (t & 1) << 1;
            #pragma unroll
            for (int i = 0; i < 4; i++) {
                const int k2 = c0 + (i << 2);
                Bs[k2    ][nn] = f2h2(pb[i].x, pb[i].y);
                Bs[k2 + 1][nn] = f2h2(pb[i].z, pb[i].w);
            }
        } else {
            // pb[0]/pb[1]: row 2kp cols cb..cb+7 ; pb[2]/pb[3]: row 2kp+1
            uint4 v0, v1;
            v0.x = f2h2(pb[0].x, pb[2].x);
            v0.y = f2h2(pb[0].y, pb[2].y);
            v0.z = f2h2(pb[0].z, pb[2].z);
            v0.w = f2h2(pb[0].w, pb[2].w);
            v1.x = f2h2(pb[1].x, pb[3].x);
            v1.y = f2h2(pb[1].y, pb[3].y);
            v1.z = f2h2(pb[1].z, pb[3].z);
            v1.w = f2h2(pb[1].w, pb[3].w);
            *(uint4*)&Bs[kpNN][cbNN]     = v0;
            *(uint4*)&Bs[kpNN][cbNN + 4] = v1;
        }
    };

    // prologue
    loadA(0); loadB(0);
    storeA(); storeB();
    __syncthreads();

    for (int k0 = 0; k0 < K; k0 += 32) {
        const bool notLast = (k0 + 32 < K);
        if (notLast) { loadA(k0 + 32); loadB(k0 + 32); }

        // ---- compute on smem tile: 2 k16 steps ----
        #pragma unroll
        for (int ks = 0; ks < 2; ks++) {
            const int k2b = ks << 3;           // half2 col base
            uint32_t af[4][4], bf[4][2];
            #pragma unroll
            for (int mt = 0; mt < 4; mt++) {
                const int m0 = (warpM << 6) + (mt << 4) + grp;
                af[mt][0] = As[m0    ][k2b + tig];
                af[mt][1] = As[m0 + 8][k2b + tig];
                af[mt][2] = As[m0    ][k2b + tig + 4];
                af[mt][3] = As[m0 + 8][k2b + tig + 4];
            }
            #pragma unroll
            for (int nt = 0; nt < 4; nt++) {
                const int n0 = (warpN << 5) + (nt << 3) + grp;
                bf[nt][0] = Bs[k2b + tig    ][n0];
                bf[nt][1] = Bs[k2b + tig + 4][n0];
            }
            #pragma unroll
            for (int mt = 0; mt < 4; mt++)
                #pragma unroll
                for (int nt = 0; nt < 4; nt++)
                    asm volatile(
                        "mma.sync.aligned.m16n8k16.row.col.f32.f16.f16.f32 "
                        "{%0,%1,%2,%3}, {%4,%5,%6,%7}, {%8,%9}, {%0,%1,%2,%3};"
                        : "+f"(acc[mt][nt][0]), "+f"(acc[mt][nt][1]),
                          "+f"(acc[mt][nt][2]), "+f"(acc[mt][nt][3])
                        : "r"(af[mt][0]), "r"(af[mt][1]),
                          "r"(af[mt][2]), "r"(af[mt][3]),
                          "r"(bf[nt][0]), "r"(bf[nt][1]));
        }
        __syncthreads();

        if (notLast) {
            storeA(); storeB();
            __syncthreads();
        }
    }

    // ---- epilogue ----
    const int rowB = (blockIdx.y << 7) + (warpM << 6) + grp;
    const int colB = (blockIdx.x << 7) + (warpN << 5) + (tig << 1);

    #pragma unroll
    for (int nt = 0; nt < 4; nt++) {
        const int col = colB + (nt << 3);
        float b0 = 0.f, b1 = 0.f;
        if (HAS_BIAS) { b0 = bias[col]; b1 = bias[col + 1]; }
        #pragma unroll
        for (int mt = 0; mt < 4; mt++) {
            float v0 = acc[mt][nt][0] * alpha + b0;
            float v1 = acc[mt][nt][1] * alpha + b1;
            float v2 = acc[mt][nt][2] * alpha + b0;
            float v3 = acc[mt][nt][3] * alpha + b1;
            if (RELU) {
                v0 = fmaxf(v0, 0.f); v1 = fmaxf(v1, 0.f);
                v2 = fmaxf(v2, 0.f); v3 = fmaxf(v3, 0.f);
            }
            const int r0 = rowB + (mt << 4);
            *(float2*)(Cp + (size_t)r0 * N + col)       = make_float2(v0, v1);
            *(float2*)(Cp + (size_t)(r0 + 8) * N + col) = make_float2(v2, v3);
        }
    }
}

// ---------------------------------------------------------------------------
// Reductions
// ---------------------------------------------------------------------------
__inline__ __device__ float warpSum(float v) {
    #pragma unroll
    for (int o = 16; o > 0; o >>= 1) v += __shfl_xor_sync(0xffffffffu, v, o);
    return v;
}
__inline__ __device__ float warpMax(float v) {
    #pragma unroll
    for (int o = 16; o > 0; o >>= 1) v = fmaxf(v, __shfl_xor_sync(0xffffffffu, v, o));
    return v;
}

// LayerNorm over D=256; one block (256 threads) per row
__global__ __launch_bounds__(256)
void ln_kernel(const float* __restrict__ x, const float* __restrict__ gamma,
               const float* __restrict__ beta, float* __restrict__ out)
{
    const long long row = blockIdx.x;
    const int t = threadIdx.x;
    const float v = x[row * D_DIM + t];

    __shared__ float sh1[8], sh2[8];
    float s  = warpSum(v);
    float sq = warpSum(v * v);
    const int w = t >> 5, l = t & 31;
    if (l == 0) { sh1[w] = s; sh2[w] = sq; }
    __syncthreads();
    if (w == 0) {
        float a = (l < 8) ? sh1[l] : 0.f;
        float b = (l < 8) ? sh2[l] : 0.f;
        a = warpSum(a); b = warpSum(b);
        if (l == 0) { sh1[0] = a; sh2[0] = b; }
    }
    __syncthreads();
    const float mu  = sh1[0] * (1.0f / D_DIM);
    const float var = sh2[0] * (1.0f / D_DIM) - mu * mu;
    out[row * D_DIM + t] = (v - mu) * rsqrtf(var + 1e-5f) * gamma[t] + beta[t];
}

// Softmax over S=512; one block (128 threads, float4 each) per row, in-place
__global__ __launch_bounds__(128)
void softmax_kernel(float* __restrict__ p)
{
    const long long row = blockIdx.x;
    float* pr = p + row * S_LEN;
    const int t = threadIdx.x;
    const int w = t >> 5, l = t & 31;

    float4 a = *(float4*)(pr + (t << 2));
    __shared__ float sh[4], sh2[4];

    float m = fmaxf(fmaxf(a.x, a.y), fmaxf(a.z, a.w));
    m = warpMax(m);
    if (l == 0) sh[w] = m;
    __syncthreads();
    m = fmaxf(fmaxf(sh[0], sh[1]), fmaxf(sh[2], sh[3]));

    a.x = __expf(a.x - m); a.y = __expf(a.y - m);
    a.z = __expf(a.z - m); a.w = __expf(a.w - m);
    float s = warpSum(a.x + a.y + a.z + a.w);
    if (l == 0) sh2[w] = s;
    __syncthreads();
    const float inv = 1.0f / (sh2[0] + sh2[1] + sh2[2] + sh2[3]);

    a.x *= inv; a.y *= inv; a.z *= inv; a.w *= inv;
    *(float4*)(pr + (t << 2)) = a;
}

// Per-channel mean over S*D = 131072 elements (float4)
__global__ __launch_bounds__(256)
void chmean_kernel(const float* __restrict__ h, float* __restrict__ y)
{
    const int c = blockIdx.x;
    const float4* hc = (const float4*)(h + (long long)c * S_LEN * D_DIM);
    float s = 0.f;
    for (int i = threadIdx.x; i < S_LEN * D_DIM / 4; i += 256) {
        float4 v = hc[i];
        s += (v.x + v.y) + (v.z + v.w);
    }
    __shared__ float sh[8];
    const int w = threadIdx.x >> 5, l = threadIdx.x & 31;
    s = warpSum(s);
    if (l == 0) sh[w] = s;
    __syncthreads();
    if (w == 0) {
        float v = (l < 8) ? sh[l] : 0.f;
        v = warpSum(v);
        if (l == 0) y[c] = v * (1.0f / (S_LEN * D_DIM));
    }
}

// SE gate: g = sigmoid(relu(y @ W1 + b1) @ W2 + b2); single block
__global__ __launch_bounds__(256)
void se_kernel(const float* __restrict__ y,
               const float* __restrict__ W1, const float* __restrict__ b1,
               const float* __restrict__ W2, const float* __restrict__ b2,
               float* __restrict__ gate)
{
    __shared__ float ys[C_CH];
    __shared__ float hid[16];
    const int t = threadIdx.x;
    ys[t] = y[t];
    __syncthreads();
    if (t < 16) {
        float s = b1[t];
        #pragma unroll 8
        for (int c = 0; c < C_CH; c++) s += ys[c] * W1[c * 16 + t];
        hid[t] = fmaxf(s, 0.f);
    }
    __syncthreads();
    float s = b2[t];
    #pragma unroll
    for (int j = 0; j < 16; j++) s += hid[j] * W2[j * C_CH + t];
    gate[t] = 1.0f / (1.0f + __expf(-s));
}

// out = h * gate[c] + x   (h already in `out`), float4
__global__ __launch_bounds__(256)
void final_kernel(float* __restrict__ out, const float* __restrict__ x,
                  const float* __restrict__ gate)
{
    const long long i4 = (long long)blockIdx.x * 256 + threadIdx.x;
    const int c = (int)(i4 >> 15);        // (i4*4) >> 17
    const float g = gate[c];
    float4 h = ((float4*)out)[i4];
    float4 xv = ((const float4*)x)[i4];
    h.x = h.x * g + xv.x;
    h.y = h.y * g + xv.y;
    h.z = h.z * g + xv.z;
    h.w = h.w * g + xv.w;
    ((float4*)out)[i4] = h;
}

// ---------------------------------------------------------------------------
// Launch
// ---------------------------------------------------------------------------
extern "C" void kernel_launch(void* const* d_in, const int* in_sizes, int n_in,
                              void* d_out, int out_size)
{
    const float* input = (const float*)d_in[0];
    const float* W_emb = (const float*)d_in[1];
    const float* b_emb = (const float*)d_in[2];
    const float* ln_g  = (const float*)d_in[3];
    const float* ln_b  = (const float*)d_in[4];
    const float* W1    = (const float*)d_in[5];
    const float* b1    = (const float*)d_in[6];
    const float* W2    = (const float*)d_in[7];
    const float* b2    = (const float*)d_in[8];
    const float* seW1  = (const float*)d_in[9];
    const float* seb1  = (const float*)d_in[10];
    const float* seW2  = (const float*)d_in[11];
    const float* seb2  = (const float*)d_in[12];

    float* out  = (float*)d_out;               // [C,S,D]
    float* attn = out + ELEMS;                 // [C,S,S]

    float *px, *pn, *po, *pffn, *py, *pg;
    cudaGetSymbolAddress((void**)&px,   g_x);
    cudaGetSymbolAddress((void**)&pn,   g_n);
    cudaGetSymbolAddress((void**)&po,   g_o);
    cudaGetSymbolAddress((void**)&pffn, g_ffn);
    cudaGetSymbolAddress((void**)&py,   g_y);
    cudaGetSymbolAddress((void**)&pg,   g_gate);

    const dim3 blk(256);
    const long long strideN = (long long)S_LEN * D_DIM;
    const long long strideP = (long long)S_LEN * S_LEN;

    // 1) x = input @ W_emb + b_emb             [131072,256] x [256,256]
    mma_gemm<false, false, true>
        <<<dim3(D_DIM / 128, NROWS / 128, 1), blk>>>(
            input, W_emb, b_emb, px, NROWS, D_DIM, D_IN, 1.0f, 0, 0, 0);

    // 2) n = LayerNorm(x)
    ln_kernel<<<NROWS, 256>>>(px, ln_g, ln_b, pn);

    // 3) scores = (n @ n^T) / 16   per channel  [512,512]
    mma_gemm<true, false, false>
        <<<dim3(S_LEN / 128, S_LEN / 128, C_CH), blk>>>(
            pn, pn, nullptr, attn, S_LEN, S_LEN, D_DIM, 0.0625f,
            strideN, strideN, strideP);

    // 4) attn = softmax(scores) in-place
    softmax_kernel<<<C_CH * S_LEN, 128>>>(attn);

    // 5) o = attn @ n   per channel             [512,512] x [512,256]
    mma_gemm<false, false, false>
        <<<dim3(D_DIM / 128, S_LEN / 128, C_CH), blk>>>(
            attn, pn, nullptr, po, S_LEN, D_DIM, S_LEN, 1.0f,
            strideP, strideN, strideN);

    // 6) h1 = relu(o @ W1 + b1)                 [131072,256] x [256,1024]
    mma_gemm<false, true, true>
        <<<dim3(D_FF / 128, NROWS / 128, 1), blk>>>(
            po, W1, b1, pffn, NROWS, D_FF, D_DIM, 1.0f, 0, 0, 0);

    // 7) h = h1 @ W2 + b2 -> out region         [131072,1024] x [1024,256]
    mma_gemm<false, false, true>
        <<<dim3(D_DIM / 128, NROWS / 128, 1), blk>>>(
            pffn, W2, b2, out, NROWS, D_DIM, D_FF, 1.0f, 0, 0, 0);

    // 8) y[c] = mean(h[c])
    chmean_kernel<<<C_CH, 256>>>(out, py);

    // 9) SE gate
    se_kernel<<<1, 256>>>(py, seW1, seb1, seW2, seb2, pg);

    // 10) out = h * g[c] + x
    final_kernel<<<(unsigned)(ELEMS / 1024), 256>>>(out, px, pg);
}

// round 10
// speedup vs baseline: 3.0001x; 1.0018x over previous
#include <cuda_runtime.h>
#include <cuda_fp16.h>
#include <stdint.h>

// Problem constants
#define C_CH   256
#define S_LEN  512
#define D_DIM  256
#define D_IN   256
#define D_FF   1024
#define NROWS  (C_CH * S_LEN)              // 131072
#define ELEMS  ((long long)NROWS * D_DIM)  // 33,554,432

// ---------------------------------------------------------------------------
// Scratch
// ---------------------------------------------------------------------------
__device__ float g_x  [NROWS * D_DIM];
__device__ float g_n  [NROWS * D_DIM];
__device__ float g_o  [NROWS * D_DIM];
__device__ float g_ffn[NROWS * D_FF];
__device__ float g_y  [C_CH];
__device__ float g_gate[C_CH];

// pack two floats into half2 (lo = a, hi = b)
__device__ __forceinline__ uint32_t f2h2(float a, float b) {
    __half2 h = __floats2half2_rn(a, b);
    return *(uint32_t*)&h;
}

// ---------------------------------------------------------------------------
// FP16 tensor-core GEMM (fp32 accumulate):
//   C = alpha * A @ B(^T) [+bias] [relu], batch = blockIdx.z
//   A: [M,K] row-major. B: NN -> [K,N]; NT -> [N,K].
//   Tile 128x128x32, 256 threads = 8 warps (2 x 4), 64x32 per warp.
//   mma.sync m16n8k16.f16 with f32 accumulators.
//   M,N multiples of 128; K multiples of 32 -> no bounds checks.
//   Smem holds half2 (uint32 = 2 consecutive K values).
// ---------------------------------------------------------------------------
template<bool TRANS_B, bool RELU, bool HAS_BIAS>
__global__ __launch_bounds__(256)
void mma_gemm(const float* __restrict__ Aall, const float* __restrict__ Ball,
              const float* __restrict__ bias, float* __restrict__ Call,
              int M, int N, int K, float alpha,
              long long sA, long long sB, long long sC)
{
    const float* A  = Aall + (long long)blockIdx.z * sA;
    const float* B  = Ball + (long long)blockIdx.z * sB;
    float*       Cp = Call + (long long)blockIdx.z * sC;

    // A[m][k2]: 16 half2 cols + 4 pad -> frag banks (20*grp + tig)%32 distinct
    __shared__ uint32_t As[128][20];
    // B[k2][n]: 128 cols + 8 pad -> frag banks (8*tig + grp)%32 distinct
    __shared__ uint32_t Bs[16][136];

    const int t     = threadIdx.x;
    const int lane  = t & 31;
    const int warp  = t >> 5;
    const int warpM = warp >> 2;   // 0..1
    const int warpN = warp & 3;    // 0..3
    const int grp   = lane >> 2;
    const int tig   = lane & 3;

    // --- global loaders --------------------------------------------------
    // A: thread t -> row t>>1, float4 at k = 4*(t&1) + 8*i  (i = 0..3)
    const int aRow = (blockIdx.y << 7) + (t >> 1);
    const int kSub = (t & 1) << 2;
    const float* aPtr = A + (size_t)aRow * K + kSub;

    const float* bPtr;
    int kpNN = 0, cbNN = 0;
    if (TRANS_B) {
        // B[N,K]: row n = bx*128 + t>>1, float4 at k = 4*(t&1) + 8*i
        const int bRow = (blockIdx.x << 7) + (t >> 1);
        bPtr = B + (size_t)bRow * K + kSub;
    } else {
        // B[K,N]: thread t -> k-pair kp = t>>4 (rows 2kp, 2kp+1),
        //         8 n-cols at cb = 8*(t&15)
        kpNN = t >> 4;
        cbNN = (t & 15) << 3;
        bPtr = B + (size_t)(kpNN << 1) * N + (blockIdx.x << 7) + cbNN;
    }

    float acc[4][4][4];
    #pragma unroll
    for (int i = 0; i < 4; i++)
        #pragma unroll
        for (int j = 0; j < 4; j++)
            #pragma unroll
            for (int r = 0; r < 4; r++) acc[i][j][r] = 0.0f;

    float4 pa[4], pb[4];

    // ---- global load helpers (offset = k0 of slab) ----
    auto loadA = [&](int k0) {
        const float* ap = aPtr + k0;
        #pragma unroll
        for (int i = 0; i < 4; i++) pa[i] = *(const float4*)(ap + (i << 3));
    };
    auto loadB = [&](int k0) {
        if (TRANS_B) {
            const float* bp = bPtr + k0;
            #pragma unroll
            for (int i = 0; i < 4; i++) pb[i] = *(const float4*)(bp + (i << 3));
        } else {
            const float* bp = bPtr + (size_t)k0 * N;
            pb[0] = *(const float4*)(bp);
            pb[1] = *(const float4*)(bp + 4);
            pb[2] = *(const float4*)(bp + N);
            pb[3] = *(const float4*)(bp + N + 4);
        }
    };

    // ---- smem store helpers ----
    auto storeA = [&]() {
        const int row = t >> 1;
        const int c0  = (t & 1) << 1;          // half2 col base: 0 or 2
        #pragma unroll
        for (int i = 0; i < 4; i++) {
            uint2 v;
            v.x = f2h2(pa[i].x, pa[i].y);
            v.y = f2h2(pa[i].z, pa[i].w);
            *(uint2*)&As[row][c0 + (i << 2)] = v;
        }
    };
    auto storeB = [&]() {
        if (TRANS_B) {
            const int nn = t >> 1;
            const int c0 = (t & 1) << 1;
            #pragma unroll
            for (int i = 0; i < 4; i++) {
                const int k2 = c0 + (i << 2);
                Bs[k2    ][nn] = f2h2(pb[i].x, pb[i].y);
                Bs[k2 + 1][nn] = f2h2(pb[i].z, pb[i].w);
            }
        } else {
            // pb[0]/pb[1]: row 2kp cols cb..cb+7 ; pb[2]/pb[3]: row 2kp+1
            uint4 v0, v1;
            v0.x = f2h2(pb[0].x, pb[2].x);
            v0.y = f2h2(pb[0].y, pb[2].y);
            v0.z = f2h2(pb[0].z, pb[2].z);
            v0.w = f2h2(pb[0].w, pb[2].w);
            v1.x = f2h2(pb[1].x, pb[3].x);
            v1.y = f2h2(pb[1].y, pb[3].y);
            v1.z = f2h2(pb[1].z, pb[3].z);
            v1.w = f2h2(pb[1].w, pb[3].w);
            *(uint4*)&Bs[kpNN][cbNN]     = v0;
            *(uint4*)&Bs[kpNN][cbNN + 4] = v1;
        }
    };

    // prologue
    loadA(0); loadB(0);
    storeA(); storeB();
    __syncthreads();

    for (int k0 = 0; k0 < K; k0 += 32) {
        const bool notLast = (k0 + 32 < K);
        if (notLast) { loadA(k0 + 32); loadB(k0 + 32); }

        // ---- compute on smem tile: 2 k16 steps ----
        #pragma unroll
        for (int ks = 0; ks < 2; ks++) {
            const int k2b = ks << 3;           // half2 col base
            uint32_t af[4][4], bf[4][2];
            #pragma unroll
            for (int mt = 0; mt < 4; mt++) {
                const int m0 = (warpM << 6) + (mt << 4) + grp;
                af[mt][0] = As[m0    ][k2b + tig];
                af[mt][1] = As[m0 + 8][k2b + tig];
                af[mt][2] = As[m0    ][k2b + tig + 4];
                af[mt][3] = As[m0 + 8][k2b + tig + 4];
            }
            #pragma unroll
            for (int nt = 0; nt < 4; nt++) {
                const int n0 = (warpN << 5) + (nt << 3) + grp;
                bf[nt][0] = Bs[k2b + tig    ][n0];
                bf[nt][1] = Bs[k2b + tig + 4][n0];
            }
            #pragma unroll
            for (int mt = 0; mt < 4; mt++)
                #pragma unroll
                for (int nt = 0; nt < 4; nt++)
                    asm volatile(
                        "mma.sync.aligned.m16n8k16.row.col.f32.f16.f16.f32 "
                        "{%0,%1,%2,%3}, {%4,%5,%6,%7}, {%8,%9}, {%0,%1,%2,%3};"
                        : "+f"(acc[mt][nt][0]), "+f"(acc[mt][nt][1]),
                          "+f"(acc[mt][nt][2]), "+f"(acc[mt][nt][3])
                        : "r"(af[mt][0]), "r"(af[mt][1]),
                          "r"(af[mt][2]), "r"(af[mt][3]),
                          "r"(bf[nt][0]), "r"(bf[nt][1]));
        }
        __syncthreads();

        if (notLast) {
            storeA(); storeB();
            __syncthreads();
        }
    }

    // ---- epilogue ----
    const int rowB = (blockIdx.y << 7) + (warpM << 6) + grp;
    const int colB = (blockIdx.x << 7) + (warpN << 5) + (tig << 1);

    #pragma unroll
    for (int nt = 0; nt < 4; nt++) {
        const int col = colB + (nt << 3);
        float b0 = 0.f, b1 = 0.f;
        if (HAS_BIAS) { b0 = bias[col]; b1 = bias[col + 1]; }
        #pragma unroll
        for (int mt = 0; mt < 4; mt++) {
            float v0 = acc[mt][nt][0] * alpha + b0;
            float v1 = acc[mt][nt][1] * alpha + b1;
            float v2 = acc[mt][nt][2] * alpha + b0;
            float v3 = acc[mt][nt][3] * alpha + b1;
            if (RELU) {
                v0 = fmaxf(v0, 0.f); v1 = fmaxf(v1, 0.f);
                v2 = fmaxf(v2, 0.f); v3 = fmaxf(v3, 0.f);
            }
            const int r0 = rowB + (mt << 4);
            *(float2*)(Cp + (size_t)r0 * N + col)       = make_float2(v0, v1);
            *(float2*)(Cp + (size_t)(r0 + 8) * N + col) = make_float2(v2, v3);
        }
    }
}

// ---------------------------------------------------------------------------
// Reductions
// ---------------------------------------------------------------------------
__inline__ __device__ float warpSum(float v) {
    #pragma unroll
    for (int o = 16; o > 0; o >>= 1) v += __shfl_xor_sync(0xffffffffu, v, o);
    return v;
}
__inline__ __device__ float warpMax(float v) {
    #pragma unroll
    for (int o = 16; o > 0; o >>= 1) v = fmaxf(v, __shfl_xor_sync(0xffffffffu, v, o));
    return v;
}

// LayerNorm over D=256; one block (256 threads) per row
__global__ __launch_bounds__(256)
void ln_kernel(const float* __restrict__ x, const float* __restrict__ gamma,
               const float* __restrict__ beta, float* __restrict__ out)
{
    const long long row = blockIdx.x;
    const int t = threadIdx.x;
    const float v = x[row * D_DIM + t];

    __shared__ float sh1[8], sh2[8];
    float s  = warpSum(v);
    float sq = warpSum(v * v);
    const int w = t >> 5, l = t & 31;
    if (l == 0) { sh1[w] = s; sh2[w] = sq; }
    __syncthreads();
    if (w == 0) {
        float a = (l < 8) ? sh1[l] : 0.f;
        float b = (l < 8) ? sh2[l] : 0.f;
        a = warpSum(a); b = warpSum(b);
        if (l == 0) { sh1[0] = a; sh2[0] = b; }
    }
    __syncthreads();
    const float mu  = sh1[0] * (1.0f / D_DIM);
    const float var = sh2[0] * (1.0f / D_DIM) - mu * mu;
    out[row * D_DIM + t] = (v - mu) * rsqrtf(var + 1e-5f) * gamma[t] + beta[t];
}

// Softmax over S=512; one block (128 threads, float4 each) per row, in-place
__global__ __launch_bounds__(128)
void softmax_kernel(float* __restrict__ p)
{
    const long long row = blockIdx.x;
    float* pr = p + row * S_LEN;
    const int t = threadIdx.x;
    const int w = t >> 5, l = t & 31;

    float4 a = *(float4*)(pr + (t << 2));
    __shared__ float sh[4], sh2[4];

    float m = fmaxf(fmaxf(a.x, a.y), fmaxf(a.z, a.w));
    m = warpMax(m);
    if (l == 0) sh[w] = m;
    __syncthreads();
    m = fmaxf(fmaxf(sh[0], sh[1]), fmaxf(sh[2], sh[3]));

    a.x = __expf(a.x - m); a.y = __expf(a.y - m);
    a.z = __expf(a.z - m); a.w = __expf(a.w - m);
    float s = warpSum(a.x + a.y + a.z + a.w);
    if (l == 0) sh2[w] = s;
    __syncthreads();
    const float inv = 1.0f / (sh2[0] + sh2[1] + sh2[2] + sh2[3]);

    a.x *= inv; a.y *= inv; a.z *= inv; a.w *= inv;
    *(float4*)(pr + (t << 2)) = a;
}

// Per-channel mean over S*D = 131072 elements (float4)
__global__ __launch_bounds__(256)
void chmean_kernel(const float* __restrict__ h, float* __restrict__ y)
{
    const int c = blockIdx.x;
    const float4* hc = (const float4*)(h + (long long)c * S_LEN * D_DIM);
    float s = 0.f;
    for (int i = threadIdx.x; i < S_LEN * D_DIM / 4; i += 256) {
        float4 v = hc[i];
        s += (v.x + v.y) + (v.z + v.w);
    }
    __shared__ float sh[8];
    const int w = threadIdx.x >> 5, l = threadIdx.x & 31;
    s = warpSum(s);
    if (l == 0) sh[w] = s;
    __syncthreads();
    if (w == 0) {
        float v = (l < 8) ? sh[l] : 0.f;
        v = warpSum(v);
        if (l == 0) y[c] = v * (1.0f / (S_LEN * D_DIM));
    }
}

// SE gate: g = sigmoid(relu(y @ W1 + b1) @ W2 + b2); single block
__global__ __launch_bounds__(256)
void se_kernel(const float* __restrict__ y,
               const float* __restrict__ W1, const float* __restrict__ b1,
               const float* __restrict__ W2, const float* __restrict__ b2,
               float* __restrict__ gate)
{
    __shared__ float ys[C_CH];
    __shared__ float hid[16];
    const int t = threadIdx.x;
    ys[t] = y[t];
    __syncthreads();
    if (t < 16) {
        float s = b1[t];
        #pragma unroll 8
        for (int c = 0; c < C_CH; c++) s += ys[c] * W1[c * 16 + t];
        hid[t] = fmaxf(s, 0.f);
    }
    __syncthreads();
    float s = b2[t];
    #pragma unroll
    for (int j = 0; j < 16; j++) s += hid[j] * W2[j * C_CH + t];
    gate[t] = 1.0f / (1.0f + __expf(-s));
}

// out = h * gate[c] + x   (h already in `out`), float4
__global__ __launch_bounds__(256)
void final_kernel(float* __restrict__ out, const float* __restrict__ x,
                  const float* __restrict__ gate)
{
    const long long i4 = (long long)blockIdx.x * 256 + threadIdx.x;
    const int c = (int)(i4 >> 15);        // (i4*4) >> 17
    const float g = gate[c];
    float4 h = ((float4*)out)[i4];
    float4 xv = ((const float4*)x)[i4];
    h.x = h.x * g + xv.x;
    h.y = h.y * g + xv.y;
    h.z = h.z * g + xv.z;
    h.w = h.w * g + xv.w;
    ((float4*)out)[i4] = h;
}

// ---------------------------------------------------------------------------
// Launch
// ---------------------------------------------------------------------------
extern "C" void kernel_launch(void* const* d_in, const int* in_sizes, int n_in,
                              void* d_out, int out_size)
{
    const float* input = (const float*)d_in[0];
    const float* W_emb = (const float*)d_in[1];
    const float* b_emb = (const float*)d_in[2];
    const float* ln_g  = (const float*)d_in[3];
    const float* ln_b  = (const float*)d_in[4];
    const float* W1    = (const float*)d_in[5];
    const float* b1    = (const float*)d_in[6];
    const float* W2    = (const float*)d_in[7];
    const float* b2    = (const float*)d_in[8];
    const float* seW1  = (const float*)d_in[9];
    const float* seb1  = (const float*)d_in[10];
    const float* seW2  = (const float*)d_in[11];
    const float* seb2  = (const float*)d_in[12];

    float* out  = (float*)d_out;               // [C,S,D]
    float* attn = out + ELEMS;                 // [C,S,S]

    float *px, *pn, *po, *pffn, *py, *pg;
    cudaGetSymbolAddress((void**)&px,   g_x);
    cudaGetSymbolAddress((void**)&pn,   g_n);
    cudaGetSymbolAddress((void**)&po,   g_o);
    cudaGetSymbolAddress((void**)&pffn, g_ffn);
    cudaGetSymbolAddress((void**)&py,   g_y);
    cudaGetSymbolAddress((void**)&pg,   g_gate);

    const dim3 blk(256);
    const long long strideN = (long long)S_LEN * D_DIM;
    const long long strideP = (long long)S_LEN * S_LEN;

    // 1) x = input @ W_emb + b_emb             [131072,256] x [256,256]
    mma_gemm<false, false, true>
        <<<dim3(D_DIM / 128, NROWS / 128, 1), blk>>>(
            input, W_emb, b_emb, px, NROWS, D_DIM, D_IN, 1.0f, 0, 0, 0);

    // 2) n = LayerNorm(x)
    ln_kernel<<<NROWS, 256>>>(px, ln_g, ln_b, pn);

    // 3) scores = (n @ n^T) / 16   per channel  [512,512]
    mma_gemm<true, false, false>
        <<<dim3(S_LEN / 128, S_LEN / 128, C_CH), blk>>>(
            pn, pn, nullptr, attn, S_LEN, S_LEN, D_DIM, 0.0625f,
            strideN, strideN, strideP);

    // 4) attn = softmax(scores) in-place
    softmax_kernel<<<C_CH * S_LEN, 128>>>(attn);

    // 5) o = attn @ n   per channel             [512,512] x [512,256]
    mma_gemm<false, false, false>
        <<<dim3(D_DIM / 128, S_LEN / 128, C_CH), blk>>>(
            attn, pn, nullptr, po, S_LEN, D_DIM, S_LEN, 1.0f,
            strideP, strideN, strideN);

    // 6) h1 = relu(o @ W1 + b1)                 [131072,256] x [256,1024]
    mma_gemm<false, true, true>
        <<<dim3(D_FF / 128, NROWS / 128, 1), blk>>>(
            po, W1, b1, pffn, NROWS, D_FF, D_DIM, 1.0f, 0, 0, 0);

    // 7) h = h1 @ W2 + b2 -> out region         [131072,1024] x [1024,256]
    mma_gemm<false, false, true>
        <<<dim3(D_DIM / 128, NROWS / 128, 1), blk>>>(
            pffn, W2, b2, out, NROWS, D_DIM, D_FF, 1.0f, 0, 0, 0);

    // 8) y[c] = mean(h[c])
    chmean_kernel<<<C_CH, 256>>>(out, py);

    // 9) SE gate
    se_kernel<<<1, 256>>>(py, seW1, seb1, seW2, seb2, pg);

    // 10) out = h * g[c] + x
    final_kernel<<<(unsigned)(ELEMS / 1024), 256>>>(out, px, pg);
}

// round 11
// speedup vs baseline: 3.6041x; 1.2013x over previous
#include <cuda_runtime.h>
#include <cuda_fp16.h>
#include <stdint.h>

// Problem constants
#define C_CH   256
#define S_LEN  512
#define D_DIM  256
#define D_IN   256
#define D_FF   1024
#define NROWS  (C_CH * S_LEN)              // 131072
#define ELEMS  ((long long)NROWS * D_DIM)  // 33,554,432

// ---------------------------------------------------------------------------
// Scratch (static; no allocation allowed)
// ---------------------------------------------------------------------------
__device__ float  g_x   [NROWS * D_DIM];                 // 134 MB fp32 (residual)
__device__ __half g_n_h [NROWS * D_DIM];                 // 67 MB  layernorm out
__device__ __half g_nT_h[NROWS * D_DIM];                 // 67 MB  n transposed per channel
__device__ __half g_o_h [NROWS * D_DIM];                 // 67 MB  attention out
__device__ __half g_ffn_h[(size_t)NROWS * D_FF];         // 268 MB FFN hidden
__device__ __half g_attn_h[(size_t)C_CH * S_LEN * S_LEN];// 134 MB probs fp16
__device__ __half g_w1t [D_FF * D_DIM];                  // W1^T [1024,256]
__device__ __half g_w2t [D_DIM * D_FF];                  // W2^T [256,1024]
__device__ float  g_y   [C_CH];
__device__ float  g_gate[C_CH];

// pack two floats into half2-as-u32
__device__ __forceinline__ uint32_t f2h2(float a, float b) {
    __half2 h = __floats2half2_rn(a, b);
    return *(uint32_t*)&h;
}

// cp.async helpers
#define CP16(dst, src) asm volatile("cp.async.ca.shared.global [%0], [%1], 16;\n" :: "r"(dst), "l"(src))
#define CP_COMMIT()    asm volatile("cp.async.commit_group;\n")
#define CP_WAIT0()     asm volatile("cp.async.wait_group 0;\n")

// ===========================================================================
// Unified NT fp16 GEMM:  C = alpha * A @ B^T [+bias] [relu]
//   A: [M,K] half row-major,  B: [N,K] half row-major, batch via blockIdx.z.
//   Tile 128x128x32, 256 threads (8 warps 2x4), warp tile 64x32.
//   cp.async double-buffered; smem layout [row][20 u32] (stride 80B),
//   fragment LDS bank-conflict-free: (20*grp + tig) mod 32 all distinct.
//   M,N mult of 128; K mult of 32.
// ===========================================================================
template<bool OUT_HALF, bool RELU, bool HAS_BIAS>
__global__ __launch_bounds__(256)
void mma_nt(const __half* __restrict__ Aall, const __half* __restrict__ Ball,
            const float* __restrict__ bias, void* __restrict__ Call,
            int M, int N, int K, float alpha,
            long long sA, long long sB, long long sC)
{
    const __half* A = Aall + (long long)blockIdx.z * sA;
    const __half* B = Ball + (long long)blockIdx.z * sB;

    __shared__ uint32_t As[2][128][20];
    __shared__ uint32_t Bs[2][128][20];

    const int t     = threadIdx.x;
    const int lane  = t & 31;
    const int warp  = t >> 5;
    const int warpM = warp >> 2;   // 0..1
    const int warpN = warp & 3;    // 0..3
    const int grp   = lane >> 4 ? 0 : 0, dummy = 0; (void)dummy; // (placeholder removed below)
    const int g8    = lane >> 2;   // 0..7
    const int tig   = lane & 3;    // 0..3

    // loader: each thread owns 32B of one row per slab (2 x 16B cp.async per operand)
    const int lRow = t >> 1;
    const int lOff = (t & 1) << 4;               // 16 halves = 32B
    const __half* aSrc = A + (size_t)((blockIdx.y << 7) + lRow) * K + lOff;
    const __half* bSrc = B + (size_t)((blockIdx.x << 7) + lRow) * K + lOff;

    uint32_t aDst[2], bDst[2];
    aDst[0] = (uint32_t)__cvta_generic_to_shared(&As[0][lRow][(t & 1) << 3]);
    aDst[1] = (uint32_t)__cvta_generic_to_shared(&As[1][lRow][(t & 1) << 3]);
    bDst[0] = (uint32_t)__cvta_generic_to_shared(&Bs[0][lRow][(t & 1) << 3]);
    bDst[1] = (uint32_t)__cvta_generic_to_shared(&Bs[1][lRow][(t & 1) << 3]);

    float acc[4][4][4];
    #pragma unroll
    for (int i = 0; i < 4; i++)
        #pragma unroll
        for (int j = 0; j < 4; j++)
            #pragma unroll
            for (int r = 0; r < 4; r++) acc[i][j][r] = 0.0f;

    const int nslabs = K >> 5;

    // prologue: slab 0 -> buf 0
    CP16(aDst[0],      aSrc);
    CP16(aDst[0] + 16, aSrc + 8);
    CP16(bDst[0],      bSrc);
    CP16(bDst[0] + 16, bSrc + 8);
    CP_COMMIT();

    for (int i = 0; i < nslabs; i++) {
        CP_WAIT0();
        __syncthreads();                 // buf i%2 ready; all warps done reading buf (i+1)%2

        if (i + 1 < nslabs) {
            const int nb = (i + 1) & 1;
            const __half* as = aSrc + ((i + 1) << 5);
            const __half* bs = bSrc + ((i + 1) << 5);
            CP16(aDst[nb],      as);
            CP16(aDst[nb] + 16, as + 8);
            CP16(bDst[nb],      bs);
            CP16(bDst[nb] + 16, bs + 8);
            CP_COMMIT();
        }

        const uint32_t (*Ab)[20] = As[i & 1];
        const uint32_t (*Bb)[20] = Bs[i & 1];

        #pragma unroll
        for (int ks = 0; ks < 2; ks++) {
            const int k2b = ks << 3;                 // half2 col base
            uint32_t af[4][4], bf[4][2];
            #pragma unroll
            for (int mt = 0; mt < 4; mt++) {
                const int m0 = (warpM << 6) + (mt << 4) + g8;
                af[mt][0] = Ab[m0    ][k2b + tig];
                af[mt][1] = Ab[m0 + 8][k2b + tig];
                af[mt][2] = Ab[m0    ][k2b + tig + 4];
                af[mt][3] = Ab[m0 + 8][k2b + tig + 4];
            }
            #pragma unroll
            for (int nt = 0; nt < 4; nt++) {
                const int n0 = (warpN << 5) + (nt << 3) + g8;
                bf[nt][0] = Bb[n0][k2b + tig];
                bf[nt][1] = Bb[n0][k2b + tig + 4];
            }
            #pragma unroll
            for (int mt = 0; mt < 4; mt++)
                #pragma unroll
                for (int nt = 0; nt < 4; nt++)
                    asm volatile(
                        "mma.sync.aligned.m16n8k16.row.col.f32.f16.f16.f32 "
                        "{%0,%1,%2,%3}, {%4,%5,%6,%7}, {%8,%9}, {%0,%1,%2,%3};"
                        : "+f"(acc[mt][nt][0]), "+f"(acc[mt][nt][1]),
                          "+f"(acc[mt][nt][2]), "+f"(acc[mt][nt][3])
                        : "r"(af[mt][0]), "r"(af[mt][1]),
                          "r"(af[mt][2]), "r"(af[mt][3]),
                          "r"(bf[nt][0]), "r"(bf[nt][1]));
        }
    }

    // ---- epilogue ----
    const int rowB = (blockIdx.y << 7) + (warpM << 6) + g8;
    const int colB = (blockIdx.x << 7) + (warpN << 5) + (tig << 1);

    #pragma unroll
    for (int nt = 0; nt < 4; nt++) {
        const int col = colB + (nt << 3);
        float b0 = 0.f, b1 = 0.f;
        if (HAS_BIAS) { b0 = bias[col]; b1 = bias[col + 1]; }
        #pragma unroll
        for (int mt = 0; mt < 4; mt++) {
            float v0 = acc[mt][nt][0] * alpha + b0;
            float v1 = acc[mt][nt][1] * alpha + b1;
            float v2 = acc[mt][nt][2] * alpha + b0;
            float v3 = acc[mt][nt][3] * alpha + b1;
            if (RELU) {
                v0 = fmaxf(v0, 0.f); v1 = fmaxf(v1, 0.f);
                v2 = fmaxf(v2, 0.f); v3 = fmaxf(v3, 0.f);
            }
            const int r0 = rowB + (mt << 4);
            if (OUT_HALF) {
                __half* Cp = (__half*)Call + (long long)blockIdx.z * sC;
                *(__half2*)(Cp + (size_t)r0 * N + col)       = __floats2half2_rn(v0, v1);
                *(__half2*)(Cp + (size_t)(r0 + 8) * N + col) = __floats2half2_rn(v2, v3);
            } else {
                float* Cp = (float*)Call + (long long)blockIdx.z * sC;
                *(float2*)(Cp + (size_t)r0 * N + col)       = make_float2(v0, v1);
                *(float2*)(Cp + (size_t)(r0 + 8) * N + col) = make_float2(v2, v3);
            }
        }
    }
}

// ===========================================================================
// Embedding GEMM (fp32 gmem operands, convert in-kernel) — R10-proven NN path.
// C = A @ B + bias.  A:[M,K] fp32, B:[K,N] fp32.
// ===========================================================================
__global__ __launch_bounds__(256)
void mma_emb(const float* __restrict__ A, const float* __restrict__ B,
             const float* __restrict__ bias, float* __restrict__ Cp,
             int M, int N, int K)
{
    __shared__ uint32_t As[128][20];
    __shared__ uint32_t Bs[16][136];

    const int t     = threadIdx.x;
    const int lane  = t & 31;
    const int warp  = t >> 5;
    const int warpM = warp >> 2;
    const int warpN = warp & 3;
    const int grp   = lane >> 2;
    const int tig   = lane & 3;

    const int aRow = (blockIdx.y << 7) + (t >> 1);
    const int kSub = (t & 1) << 2;
    const float* aPtr = A + (size_t)aRow * K + kSub;

    const int kpNN = t >> 4;
    const int cbNN = (t & 15) << 3;
    const float* bPtr = B + (size_t)(kpNN << 1) * N + (blockIdx.x << 7) + cbNN;

    float acc[4][4][4];
    #pragma unroll
    for (int i = 0; i < 4; i++)
        #pragma unroll
        for (int j = 0; j < 4; j++)
            #pragma unroll
            for (int r = 0; r < 4; r++) acc[i][j][r] = 0.0f;

    float4 pa[4], pb[4];

    auto loadA = [&](int k0) {
        const float* ap = aPtr + k0;
        #pragma unroll
        for (int i = 0; i < 4; i++) pa[i] = *(const float4*)(ap + (i << 3));
    };
    auto loadB = [&](int k0) {
        const float* bp = bPtr + (size_t)k0 * N;
        pb[0] = *(const float4*)(bp);
        pb[1] = *(const float4*)(bp + 4);
        pb[2] = *(const float4*)(bp + N);
        pb[3] = *(const float4*)(bp + N + 4);
    };
    auto storeA = [&]() {
        const int row = t >> 1;
        const int c0  = (t & 1) << 1;
        #pragma unroll
        for (int i = 0; i < 4; i++) {
            uint2 v;
            v.x = f2h2(pa[i].x, pa[i].y);
            v.y = f2h2(pa[i].z, pa[i].w);
            *(uint2*)&As[row][c0 + (i << 2)] = v;
        }
    };
    auto storeB = [&]() {
        uint4 v0, v1;
        v0.x = f2h2(pb[0].x, pb[2].x);
        v0.y = f2h2(pb[0].y, pb[2].y);
        v0.z = f2h2(pb[0].z, pb[2].z);
        v0.w = f2h2(pb[0].w, pb[2].w);
        v1.x = f2h2(pb[1].x, pb[3].x);
        v1.y = f2h2(pb[1].y, pb[3].y);
        v1.z = f2h2(pb[1].z, pb[3].z);
        v1.w = f2h2(pb[1].w, pb[3].w);
        *(uint4*)&Bs[kpNN][cbNN]     = v0;
        *(uint4*)&Bs[kpNN][cbNN + 4] = v1;
    };

    loadA(0); loadB(0);
    storeA(); storeB();
    __syncthreads();

    for (int k0 = 0; k0 < K; k0 += 32) {
        const bool notLast = (k0 + 32 < K);
        if (notLast) { loadA(k0 + 32); loadB(k0 + 32); }

        #pragma unroll
        for (int ks = 0; ks < 2; ks++) {
            const int k2b = ks << 3;
            uint32_t af[4][4], bf[4][2];
            #pragma unroll
            for (int mt = 0; mt < 4; mt++) {
                const int m0 = (warpM << 6) + (mt << 4) + grp;
                af[mt][0] = As[m0    ][k2b + tig];
                af[mt][1] = As[m0 + 8][k2b + tig];
                af[mt][2] = As[m0    ][k2b + tig + 4];
                af[mt][3] = As[m0 + 8][k2b + tig + 4];
            }
            #pragma unroll
            for (int nt = 0; nt < 4; nt++) {
                const int n0 = (warpN << 5) + (nt << 3) + grp;
                bf[nt][0] = Bs[k2b + tig    ][n0];
                bf[nt][1] = Bs[k2b + tig + 4][n0];
            }
            #pragma unroll
            for (int mt = 0; mt < 4; mt++)
                #pragma unroll
                for (int nt = 0; nt < 4; nt++)
                    asm volatile(
                        "mma.sync.aligned.m16n8k16.row.col.f32.f16.f16.f32 "
                        "{%0,%1,%2,%3}, {%4,%5,%6,%7}, {%8,%9}, {%0,%1,%2,%3};"
                        : "+f"(acc[mt][nt][0]), "+f"(acc[mt][nt][1]),
                          "+f"(acc[mt][nt][2]), "+f"(acc[mt][nt][3])
                        : "r"(af[mt][0]), "r"(af[mt][1]),
                          "r"(af[mt][2]), "r"(af[mt][3]),
                          "r"(bf[nt][0]), "r"(bf[nt][1]));
        }
        __syncthreads();

        if (notLast) {
            storeA(); storeB();
            __syncthreads();
        }
    }

    const int rowB = (blockIdx.y << 7) + (warpM << 6) + grp;
    const int colB = (blockIdx.x << 7) + (warpN << 5) + (tig << 1);

    #pragma unroll
    for (int nt = 0; nt < 4; nt++) {
        const int col = colB + (nt << 3);
        const float b0 = bias[col], b1 = bias[col + 1];
        #pragma unroll
        for (int mt = 0; mt < 4; mt++) {
            const int r0 = rowB + (mt << 4);
            *(float2*)(Cp + (size_t)r0 * N + col) =
                make_float2(acc[mt][nt][0] + b0, acc[mt][nt][1] + b1);
            *(float2*)(Cp + (size_t)(r0 + 8) * N + col) =
                make_float2(acc[mt][nt][2] + b0, acc[mt][nt][3] + b1);
        }
    }
}

// ---------------------------------------------------------------------------
// Transposes
// ---------------------------------------------------------------------------
// half [z][R][C] -> half [z][C][R]
__global__ __launch_bounds__(256)
void transpose_h(const __half* __restrict__ in, __half* __restrict__ out,
                 int R, int C)
{
    __shared__ __half tile[32][33];
    const size_t base = (size_t)blockIdx.z * R * C;
    const int x0 = blockIdx.x << 5, y0 = blockIdx.y << 5;
    const int tx = threadIdx.x & 31, ty = threadIdx.x >> 5;
    #pragma unroll
    for (int j = 0; j < 4; j++) {
        const int r = y0 + ty + (j << 3);
        tile[ty + (j << 3)][tx] = in[base + (size_t)r * C + x0 + tx];
    }
    __syncthreads();
    #pragma unroll
    for (int j = 0; j < 4; j++) {
        const int c = x0 + ty + (j << 3);
        out[base + (size_t)c * R + y0 + tx] = tile[tx][ty + (j << 3)];
    }
}

// float [R][C] -> half [C][R]
__global__ __launch_bounds__(256)
void transpose_f2h(const float* __restrict__ in, __half* __restrict__ out,
                   int R, int C)
{
    __shared__ float tile[32][33];
    const int x0 = blockIdx.x << 5, y0 = blockIdx.y << 5;
    const int tx = threadIdx.x & 31, ty = threadIdx.x >> 5;
    #pragma unroll
    for (int j = 0; j < 4; j++) {
        const int r = y0 + ty + (j << 3);
        tile[ty + (j << 3)][tx] = in[(size_t)r * C + x0 + tx];
    }
    __syncthreads();
    #pragma unroll
    for (int j = 0; j < 4; j++) {
        const int c = x0 + ty + (j << 3);
        out[(size_t)c * R + y0 + tx] = __float2half_rn(tile[tx][ty + (j << 3)]);
    }
}

// ---------------------------------------------------------------------------
// Reductions / elementwise
// ---------------------------------------------------------------------------
__inline__ __device__ float warpSum(float v) {
    #pragma unroll
    for (int o = 16; o > 0; o >>= 1) v += __shfl_xor_sync(0xffffffffu, v, o);
    return v;
}
__inline__ __device__ float warpMax(float v) {
    #pragma unroll
    for (int o = 16; o > 0; o >>= 1) v = fmaxf(v, __shfl_xor_sync(0xffffffffu, v, o));
    return v;
}

// LayerNorm over D=256; writes fp16
__global__ __launch_bounds__(256)
void ln_kernel(const float* __restrict__ x, const float* __restrict__ gamma,
               const float* __restrict__ beta, __half* __restrict__ out)
{
    const long long row = blockIdx.x;
    const int t = threadIdx.x;
    const float v = x[row * D_DIM + t];

    __shared__ float sh1[8], sh2[8];
    float s  = warpSum(v);
    float sq = warpSum(v * v);
    const int w = t >> 5, l = t & 31;
    if (l == 0) { sh1[w] = s; sh2[w] = sq; }
    __syncthreads();
    if (w == 0) {
        float a = (l < 8) ? sh1[l] : 0.f;
        float b = (l < 8) ? sh2[l] : 0.f;
        a = warpSum(a); b = warpSum(b);
        if (l == 0) { sh1[0] = a; sh2[0] = b; }
    }
    __syncthreads();
    const float mu  = sh1[0] * (1.0f / D_DIM);
    const float var = sh2[0] * (1.0f / D_DIM) - mu * mu;
    const float r = (v - mu) * rsqrtf(var + 1e-5f) * gamma[t] + beta[t];
    out[row * D_DIM + t] = __float2half_rn(r);
}

// Softmax over S=512 in-place (fp32) + fp16 copy
__global__ __launch_bounds__(128)
void softmax_kernel(float* __restrict__ p, __half* __restrict__ ph_all)
{
    const long long row = blockIdx.x;
    float* pr = p + row * S_LEN;
    __half* ph = ph_all + row * S_LEN;
    const int t = threadIdx.x;
    const int w = t >> 5, l = t & 31;

    float4 a = *(float4*)(pr + (t << 2));
    __shared__ float sh[4], sh2[4];

    float m = fmaxf(fmaxf(a.x, a.y), fmaxf(a.z, a.w));
    m = warpMax(m);
    if (l == 0) sh[w] = m;
    __syncthreads();
    m = fmaxf(fmaxf(sh[0], sh[1]), fmaxf(sh[2], sh[3]));

    a.x = __expf(a.x - m); a.y = __expf(a.y - m);
    a.z = __expf(a.z - m); a.w = __expf(a.w - m);
    float s = warpSum(a.x + a.y + a.z + a.w);
    if (l == 0) sh2[w] = s;
    __syncthreads();
    const float inv = 1.0f / (sh2[0] + sh2[1] + sh2[2] + sh2[3]);

    a.x *= inv; a.y *= inv; a.z *= inv; a.w *= inv;
    *(float4*)(pr + (t << 2)) = a;
    *(__half2*)(ph + (t << 2))     = __floats2half2_rn(a.x, a.y);
    *(__half2*)(ph + (t << 2) + 2) = __floats2half2_rn(a.z, a.w);
}

// Per-channel mean over S*D elements (float4)
__global__ __launch_bounds__(256)
void chmean_kernel(const float* __restrict__ h, float* __restrict__ y)
{
    const int c = blockIdx.x;
    const float4* hc = (const float4*)(h + (long long)c * S_LEN * D_DIM);
    float s = 0.f;
    for (int i = threadIdx.x; i < S_LEN * D_DIM / 4; i += 256) {
        float4 v = hc[i];
        s += (v.x + v.y) + (v.z + v.w);
    }
    __shared__ float sh[8];
    const int w = threadIdx.x >> 5, l = threadIdx.x & 31;
    s = warpSum(s);
    if (l == 0) sh[w] = s;
    __syncthreads();
    if (w == 0) {
        float v = (l < 8) ? sh[l] : 0.f;
        v = warpSum(v);
        if (l == 0) y[c] = v * (1.0f / (S_LEN * D_DIM));
    }
}

// SE gate
__global__ __launch_bounds__(256)
void se_kernel(const float* __restrict__ y,
               const float* __restrict__ W1, const float* __restrict__ b1,
               const float* __restrict__ W2, const float* __restrict__ b2,
               float* __restrict__ gate)
{
    __shared__ float ys[C_CH];
    __shared__ float hid[16];
    const int t = threadIdx.x;
    ys[t] = y[t];
    __syncthreads();
    if (t < 16) {
        float s = b1[t];
        #pragma unroll 8
        for (int c = 0; c < C_CH; c++) s += ys[c] * W1[c * 16 + t];
        hid[t] = fmaxf(s, 0.f);
    }
    __syncthreads();
    float s = b2[t];
    #pragma unroll
    for (int j = 0; j < 16; j++) s += hid[j] * W2[j * C_CH + t];
    gate[t] = 1.0f / (1.0f + __expf(-s));
}

// out = h * gate[c] + x
__global__ __launch_bounds__(256)
void final_kernel(float* __restrict__ out, const float* __restrict__ x,
                  const float* __restrict__ gate)
{
    const long long i4 = (long long)blockIdx.x * 256 + threadIdx.x;
    const int c = (int)(i4 >> 15);
    const float g = gate[c];
    float4 h = ((float4*)out)[i4];
    float4 xv = ((const float4*)x)[i4];
    h.x = h.x * g + xv.x;
    h.y = h.y * g + xv.y;
    h.z = h.z * g + xv.z;
    h.w = h.w * g + xv.w;
    ((float4*)out)[i4] = h;
}

// ---------------------------------------------------------------------------
// Launch
// ---------------------------------------------------------------------------
extern "C" void kernel_launch(void* const* d_in, const int* in_sizes, int n_in,
                              void* d_out, int out_size)
{
    const float* input = (const float*)d_in[0];
    const float* W_emb = (const float*)d_in[1];
    const float* b_emb = (const float*)d_in[2];
    const float* ln_g  = (const float*)d_in[3];
    const float* ln_b  = (const float*)d_in[4];
    const float* W1    = (const float*)d_in[5];
    const float* b1    = (const float*)d_in[6];
    const float* W2    = (const float*)d_in[7];
    const float* b2    = (const float*)d_in[8];
    const float* seW1  = (const float*)d_in[9];
    const float* seb1  = (const float*)d_in[10];
    const float* seW2  = (const float*)d_in[11];
    const float* seb2  = (const float*)d_in[12];

    float* out  = (float*)d_out;               // [C,S,D]
    float* attn = out + ELEMS;                 // [C,S,S] fp32 (output 1)

    float  *px, *py, *pg;
    __half *pn, *pnT, *po, *pffn, *pah, *pw1t, *pw2t;
    cudaGetSymbolAddress((void**)&px,   g_x);
    cudaGetSymbolAddress((void**)&pn,   g_n_h);
    cudaGetSymbolAddress((void**)&pnT,  g_nT_h);
    cudaGetSymbolAddress((void**)&po,   g_o_h);
    cudaGetSymbolAddress((void**)&pffn, g_ffn_h);
    cudaGetSymbolAddress((void**)&pah,  g_attn_h);
    cudaGetSymbolAddress((void**)&pw1t, g_w1t);
    cudaGetSymbolAddress((void**)&pw2t, g_w2t);
    cudaGetSymbolAddress((void**)&py,   g_y);
    cudaGetSymbolAddress((void**)&pg,   g_gate);

    const dim3 blk(256);
    const long long strideN = (long long)S_LEN * D_DIM;   // 131072
    const long long strideP = (long long)S_LEN * S_LEN;   // 262144

    // 0) weight transposes (fp32 -> fp16, transposed)
    transpose_f2h<<<dim3(D_FF / 32, D_DIM / 32), blk>>>(W1, pw1t, D_DIM, D_FF);
    transpose_f2h<<<dim3(D_DIM / 32, D_FF / 32), blk>>>(W2, pw2t, D_FF, D_DIM);

    // 1) x = input @ W_emb + b_emb  (fp32 operands)
    mma_emb<<<dim3(D_DIM / 128, NROWS / 128), blk>>>(
        input, W_emb, b_emb, px, NROWS, D_DIM, D_IN);

    // 2) n = LayerNorm(x) -> fp16
    ln_kernel<<<NROWS, 256>>>(px, ln_g, ln_b, pn);

    // 3) nT per channel: [s][d] -> [d][s]
    transpose_h<<<dim3(D_DIM / 32, S_LEN / 32, C_CH), blk>>>(pn, pnT, S_LEN, D_DIM);

    // 4) scores = (n @ n^T)/16 per channel -> attn fp32
    mma_nt<false, false, false><<<dim3(S_LEN / 128, S_LEN / 128, C_CH), blk>>>(
        pn, pn, nullptr, attn, S_LEN, S_LEN, D_DIM, 0.0625f,
        strideN, strideN, strideP);

    // 5) softmax in-place + fp16 copy
    softmax_kernel<<<C_CH * S_LEN, 128>>>(attn, pah);

    // 6) o = attn @ n per channel: NT with B = nT  -> fp16 out
    mma_nt<true, false, false><<<dim3(D_DIM / 128, S_LEN / 128, C_CH), blk>>>(
        pah, pnT, nullptr, po, S_LEN, D_DIM, S_LEN, 1.0f,
        strideP, strideN, strideN);

    // 7) h1 = relu(o @ W1 + b1): NT with B = W1T [1024,256] -> fp16
    mma_nt<true, true, true><<<dim3(D_FF / 128, NROWS / 128, 1), blk>>>(
        po, pw1t, b1, pffn, NROWS, D_FF, D_DIM, 1.0f, 0, 0, 0);

    // 8) h = h1 @ W2 + b2: NT with B = W2T [256,1024] -> fp32 out region
    mma_nt<false, false, true><<<dim3(D_DIM / 128, NROWS / 128, 1), blk>>>(
        pffn, pw2t, b2, out, NROWS, D_DIM, D_FF, 1.0f, 0, 0, 0);

    // 9) y[c] = mean(h[c])
    chmean_kernel<<<C_CH, 256>>>(out, py);

    // 10) SE gate
    se_kernel<<<1, 256>>>(py, seW1, seb1, seW2, seb2, pg);

    // 11) out = h * g[c] + x
    final_kernel<<<(unsigned)(ELEMS / 1024), 256>>>(out, px, pg);
}

// round 12
// speedup vs baseline: 4.1362x; 1.1477x over previous
#include <cuda_runtime.h>
#include <cuda_fp16.h>
#include <stdint.h>

// Problem constants
#define C_CH   256
#define S_LEN  512
#define D_DIM  256
#define D_IN   256
#define D_FF   1024
#define NROWS  (C_CH * S_LEN)              // 131072
#define ELEMS  ((long long)NROWS * D_DIM)  // 33,554,432

// ---------------------------------------------------------------------------
// Scratch (static; no allocation allowed)
// ---------------------------------------------------------------------------
__device__ float  g_x   [NROWS * D_DIM];                 // fp32 residual
__device__ __half g_n_h [NROWS * D_DIM];                 // layernorm out
__device__ __half g_nT_h[NROWS * D_DIM];                 // n transposed per channel
__device__ __half g_o_h [NROWS * D_DIM];                 // attention out
__device__ __half g_ffn_h[(size_t)NROWS * D_FF];         // FFN hidden
__device__ __half g_attn_h[(size_t)C_CH * S_LEN * S_LEN];// probs fp16
__device__ __half g_w1t [D_FF * D_DIM];                  // W1^T [1024,256]
__device__ __half g_w2t [D_DIM * D_FF];                  // W2^T [256,1024]
__device__ float  g_y   [C_CH];
__device__ float  g_gate[C_CH];

__device__ __forceinline__ uint32_t f2h2(float a, float b) {
    __half2 h = __floats2half2_rn(a, b);
    return *(uint32_t*)&h;
}

// cp.async (L2-only path) helpers
#define CP16(dst, src) asm volatile("cp.async.cg.shared.global [%0], [%1], 16;\n" :: "r"(dst), "l"(src))
#define CP_COMMIT()    asm volatile("cp.async.commit_group;\n")
#define CP_WAIT0()     asm volatile("cp.async.wait_group 0;\n")

__device__ __forceinline__ void ldsmx4(uint32_t& r0, uint32_t& r1,
                                       uint32_t& r2, uint32_t& r3, uint32_t a) {
    asm volatile("ldmatrix.sync.aligned.m8n8.x4.shared.b16 {%0,%1,%2,%3}, [%4];"
                 : "=r"(r0), "=r"(r1), "=r"(r2), "=r"(r3) : "r"(a));
}
__device__ __forceinline__ void ldsmx2(uint32_t& r0, uint32_t& r1, uint32_t a) {
    asm volatile("ldmatrix.sync.aligned.m8n8.x2.shared.b16 {%0,%1}, [%2];"
                 : "=r"(r0), "=r"(r1) : "r"(a));
}

// ===========================================================================
// Unified NT fp16 GEMM:  C = alpha * A @ B^T [+bias] [relu]
//   A: [M,K] half row-major,  B: [N,K] half row-major, batch via blockIdx.z.
//   Tile 128x128x32, 256 threads (8 warps 2x4), warp tile 64x32.
//   cp.async double-buffered; smem [row][20 u32] (80B stride) — conflict-free
//   for both cp.async stores and ldmatrix phase reads.
// ===========================================================================
template<bool OUT_HALF, bool RELU, bool HAS_BIAS>
__global__ __launch_bounds__(256)
void mma_nt(const __half* __restrict__ Aall, const __half* __restrict__ Ball,
            const float* __restrict__ bias, void* __restrict__ Call,
            int M, int N, int K, float alpha,
            long long sA, long long sB, long long sC)
{
    const __half* A = Aall + (long long)blockIdx.z * sA;
    const __half* B = Ball + (long long)blockIdx.z * sB;

    __shared__ uint32_t As[2][128][20];
    __shared__ uint32_t Bs[2][128][20];

    const int t     = threadIdx.x;
    const int lane  = t & 31;
    const int warp  = t >> 5;
    const int warpM = warp >> 2;   // 0..1
    const int warpN = warp & 3;    // 0..3
    const int g8    = lane >> 2;   // 0..7
    const int tig   = lane & 3;    // 0..3

    // global loader: thread t -> row t>>1, 32B chunk (t&1)
    const int lRow = t >> 1;
    const int lOff = (t & 1) << 4;
    const __half* aSrc = A + (size_t)((blockIdx.y << 7) + lRow) * K + lOff;
    const __half* bSrc = B + (size_t)((blockIdx.x << 7) + lRow) * K + lOff;

    uint32_t aDst[2], bDst[2];
    aDst[0] = (uint32_t)__cvta_generic_to_shared(&As[0][lRow][(t & 1) << 3]);
    aDst[1] = (uint32_t)__cvta_generic_to_shared(&As[1][lRow][(t & 1) << 3]);
    bDst[0] = (uint32_t)__cvta_generic_to_shared(&Bs[0][lRow][(t & 1) << 3]);
    bDst[1] = (uint32_t)__cvta_generic_to_shared(&Bs[1][lRow][(t & 1) << 3]);

    // ldmatrix lane base addresses (buffer 0)
    //   A x4: lanes 0-7 rows m..m+7 (k lo), 8-15 rows +8 (k lo),
    //         16-23 rows (k hi), 24-31 rows +8 (k hi)
    const uint32_t aLd0 = (uint32_t)__cvta_generic_to_shared(
        &As[0][(warpM << 6) + (lane & 15)][(lane >> 4) << 2]);
    //   B x2: lanes 0-7 rows n..n+7 (k lo), 8-15 same rows (k hi)
    const uint32_t bLd0 = (uint32_t)__cvta_generic_to_shared(
        &Bs[0][(warpN << 5) + (lane & 7)][((lane >> 3) & 1) << 2]);
    const uint32_t stageBytes = 128 * 20 * 4;   // 10240

    float acc[4][4][4];
    #pragma unroll
    for (int i = 0; i < 4; i++)
        #pragma unroll
        for (int j = 0; j < 4; j++)
            #pragma unroll
            for (int r = 0; r < 4; r++) acc[i][j][r] = 0.0f;

    const int nslabs = K >> 5;

    // prologue: slab 0 -> buf 0
    CP16(aDst[0],      aSrc);
    CP16(aDst[0] + 16, aSrc + 8);
    CP16(bDst[0],      bSrc);
    CP16(bDst[0] + 16, bSrc + 8);
    CP_COMMIT();

    for (int i = 0; i < nslabs; i++) {
        CP_WAIT0();
        __syncthreads();

        if (i + 1 < nslabs) {
            const int nb = (i + 1) & 1;
            const __half* as = aSrc + ((i + 1) << 5);
            const __half* bs = bSrc + ((i + 1) << 5);
            CP16(aDst[nb],      as);
            CP16(aDst[nb] + 16, as + 8);
            CP16(bDst[nb],      bs);
            CP16(bDst[nb] + 16, bs + 8);
            CP_COMMIT();
        }

        const uint32_t aLd = aLd0 + (i & 1) * stageBytes;
        const uint32_t bLd = bLd0 + (i & 1) * stageBytes;

        #pragma unroll
        for (int ks = 0; ks < 2; ks++) {
            uint32_t af[4][4], bf[4][2];
            #pragma unroll
            for (int mt = 0; mt < 4; mt++)
                ldsmx4(af[mt][0], af[mt][1], af[mt][2], af[mt][3],
                       aLd + mt * (16 * 80) + ks * 32);
            #pragma unroll
            for (int nt = 0; nt < 4; nt++)
                ldsmx2(bf[nt][0], bf[nt][1],
                       bLd + nt * (8 * 80) + ks * 32);
            #pragma unroll
            for (int mt = 0; mt < 4; mt++)
                #pragma unroll
                for (int nt = 0; nt < 4; nt++)
                    asm volatile(
                        "mma.sync.aligned.m16n8k16.row.col.f32.f16.f16.f32 "
                        "{%0,%1,%2,%3}, {%4,%5,%6,%7}, {%8,%9}, {%0,%1,%2,%3};"
                        : "+f"(acc[mt][nt][0]), "+f"(acc[mt][nt][1]),
                          "+f"(acc[mt][nt][2]), "+f"(acc[mt][nt][3])
                        : "r"(af[mt][0]), "r"(af[mt][1]),
                          "r"(af[mt][2]), "r"(af[mt][3]),
                          "r"(bf[nt][0]), "r"(bf[nt][1]));
        }
    }

    // ---- epilogue ----
    const int rowB = (blockIdx.y << 7) + (warpM << 6) + g8;
    const int colB = (blockIdx.x << 7) + (warpN << 5) + (tig << 1);

    #pragma unroll
    for (int nt = 0; nt < 4; nt++) {
        const int col = colB + (nt << 3);
        float b0 = 0.f, b1 = 0.f;
        if (HAS_BIAS) { b0 = bias[col]; b1 = bias[col + 1]; }
        #pragma unroll
        for (int mt = 0; mt < 4; mt++) {
            float v0 = acc[mt][nt][0] * alpha + b0;
            float v1 = acc[mt][nt][1] * alpha + b1;
            float v2 = acc[mt][nt][2] * alpha + b0;
            float v3 = acc[mt][nt][3] * alpha + b1;
            if (RELU) {
                v0 = fmaxf(v0, 0.f); v1 = fmaxf(v1, 0.f);
                v2 = fmaxf(v2, 0.f); v3 = fmaxf(v3, 0.f);
            }
            const int r0 = rowB + (mt << 4);
            if (OUT_HALF) {
                __half* Cp = (__half*)Call + (long long)blockIdx.z * sC;
                *(__half2*)(Cp + (size_t)r0 * N + col)       = __floats2half2_rn(v0, v1);
                *(__half2*)(Cp + (size_t)(r0 + 8) * N + col) = __floats2half2_rn(v2, v3);
            } else {
                float* Cp = (float*)Call + (long long)blockIdx.z * sC;
                *(float2*)(Cp + (size_t)r0 * N + col)       = make_float2(v0, v1);
                *(float2*)(Cp + (size_t)(r0 + 8) * N + col) = make_float2(v2, v3);
            }
        }
    }
}

// ===========================================================================
// Embedding GEMM (fp32 operands, convert in-kernel). C = A @ B + bias.
// ===========================================================================
__global__ __launch_bounds__(256)
void mma_emb(const float* __restrict__ A, const float* __restrict__ B,
             const float* __restrict__ bias, float* __restrict__ Cp,
             int M, int N, int K)
{
    __shared__ uint32_t As[128][20];
    __shared__ uint32_t Bs[16][136];

    const int t     = threadIdx.x;
    const int lane  = t & 31;
    const int warp  = t >> 5;
    const int warpM = warp >> 2;
    const int warpN = warp & 3;
    const int grp   = lane >> 2;
    const int tig   = lane & 3;

    const int aRow = (blockIdx.y << 7) + (t >> 1);
    const int kSub = (t & 1) << 2;
    const float* aPtr = A + (size_t)aRow * K + kSub;

    const int kpNN = t >> 4;
    const int cbNN = (t & 15) << 3;
    const float* bPtr = B + (size_t)(kpNN << 1) * N + (blockIdx.x << 7) + cbNN;

    float acc[4][4][4];
    #pragma unroll
    for (int i = 0; i < 4; i++)
        #pragma unroll
        for (int j = 0; j < 4; j++)
            #pragma unroll
            for (int r = 0; r < 4; r++) acc[i][j][r] = 0.0f;

    float4 pa[4], pb[4];

    auto loadA = [&](int k0) {
        const float* ap = aPtr + k0;
        #pragma unroll
        for (int i = 0; i < 4; i++) pa[i] = *(const float4*)(ap + (i << 3));
    };
    auto loadB = [&](int k0) {
        const float* bp = bPtr + (size_t)k0 * N;
        pb[0] = *(const float4*)(bp);
        pb[1] = *(const float4*)(bp + 4);
        pb[2] = *(const float4*)(bp + N);
        pb[3] = *(const float4*)(bp + N + 4);
    };
    auto storeA = [&]() {
        const int row = t >> 1;
        const int c0  = (t & 1) << 1;
        #pragma unroll
        for (int i = 0; i < 4; i++) {
            uint2 v;
            v.x = f2h2(pa[i].x, pa[i].y);
            v.y = f2h2(pa[i].z, pa[i].w);
            *(uint2*)&As[row][c0 + (i << 2)] = v;
        }
    };
    auto storeB = [&]() {
        uint4 v0, v1;
        v0.x = f2h2(pb[0].x, pb[2].x);
        v0.y = f2h2(pb[0].y, pb[2].y);
        v0.z = f2h2(pb[0].z, pb[2].z);
        v0.w = f2h2(pb[0].w, pb[2].w);
        v1.x = f2h2(pb[1].x, pb[3].x);
        v1.y = f2h2(pb[1].y, pb[3].y);
        v1.z = f2h2(pb[1].z, pb[3].z);
        v1.w = f2h2(pb[1].w, pb[3].w);
        *(uint4*)&Bs[kpNN][cbNN]     = v0;
        *(uint4*)&Bs[kpNN][cbNN + 4] = v1;
    };

    loadA(0); loadB(0);
    storeA(); storeB();
    __syncthreads();

    for (int k0 = 0; k0 < K; k0 += 32) {
        const bool notLast = (k0 + 32 < K);
        if (notLast) { loadA(k0 + 32); loadB(k0 + 32); }

        #pragma unroll
        for (int ks = 0; ks < 2; ks++) {
            const int k2b = ks << 3;
            uint32_t af[4][4], bf[4][2];
            #pragma unroll
            for (int mt = 0; mt < 4; mt++) {
                const int m0 = (warpM << 6) + (mt << 4) + grp;
                af[mt][0] = As[m0    ][k2b + tig];
                af[mt][1] = As[m0 + 8][k2b + tig];
                af[mt][2] = As[m0    ][k2b + tig + 4];
                af[mt][3] = As[m0 + 8][k2b + tig + 4];
            }
            #pragma unroll
            for (int nt = 0; nt < 4; nt++) {
                const int n0 = (warpN << 5) + (nt << 3) + grp;
                bf[nt][0] = Bs[k2b + tig    ][n0];
                bf[nt][1] = Bs[k2b + tig + 4][n0];
            }
            #pragma unroll
            for (int mt = 0; mt < 4; mt++)
                #pragma unroll
                for (int nt = 0; nt < 4; nt++)
                    asm volatile(
                        "mma.sync.aligned.m16n8k16.row.col.f32.f16.f16.f32 "
                        "{%0,%1,%2,%3}, {%4,%5,%6,%7}, {%8,%9}, {%0,%1,%2,%3};"
                        : "+f"(acc[mt][nt][0]), "+f"(acc[mt][nt][1]),
                          "+f"(acc[mt][nt][2]), "+f"(acc[mt][nt][3])
                        : "r"(af[mt][0]), "r"(af[mt][1]),
                          "r"(af[mt][2]), "r"(af[mt][3]),
                          "r"(bf[nt][0]), "r"(bf[nt][1]));
        }
        __syncthreads();

        if (notLast) {
            storeA(); storeB();
            __syncthreads();
        }
    }

    const int rowB = (blockIdx.y << 7) + (warpM << 6) + grp;
    const int colB = (blockIdx.x << 7) + (warpN << 5) + (tig << 1);

    #pragma unroll
    for (int nt = 0; nt < 4; nt++) {
        const int col = colB + (nt << 3);
        const float b0 = bias[col], b1 = bias[col + 1];
        #pragma unroll
        for (int mt = 0; mt < 4; mt++) {
            const int r0 = rowB + (mt << 4);
            *(float2*)(Cp + (size_t)r0 * N + col) =
                make_float2(acc[mt][nt][0] + b0, acc[mt][nt][1] + b1);
            *(float2*)(Cp + (size_t)(r0 + 8) * N + col) =
                make_float2(acc[mt][nt][2] + b0, acc[mt][nt][3] + b1);
        }
    }
}

// ---------------------------------------------------------------------------
// Transposes
// ---------------------------------------------------------------------------
__global__ __launch_bounds__(256)
void transpose_h(const __half* __restrict__ in, __half* __restrict__ out,
                 int R, int C)
{
    __shared__ __half tile[32][33];
    const size_t base = (size_t)blockIdx.z * R * C;
    const int x0 = blockIdx.x << 5, y0 = blockIdx.y << 5;
    const int tx = threadIdx.x & 31, ty = threadIdx.x >> 5;
    #pragma unroll
    for (int j = 0; j < 4; j++) {
        const int r = y0 + ty + (j << 3);
        tile[ty + (j << 3)][tx] = in[base + (size_t)r * C + x0 + tx];
    }
    __syncthreads();
    #pragma unroll
    for (int j = 0; j < 4; j++) {
        const int c = x0 + ty + (j << 3);
        out[base + (size_t)c * R + y0 + tx] = tile[tx][ty + (j << 3)];
    }
}

__global__ __launch_bounds__(256)
void transpose_f2h(const float* __restrict__ in, __half* __restrict__ out,
                   int R, int C)
{
    __shared__ float tile[32][33];
    const int x0 = blockIdx.x << 5, y0 = blockIdx.y << 5;
    const int tx = threadIdx.x & 31, ty = threadIdx.x >> 5;
    #pragma unroll
    for (int j = 0; j < 4; j++) {
        const int r = y0 + ty + (j << 3);
        tile[ty + (j << 3)][tx] = in[(size_t)r * C + x0 + tx];
    }
    __syncthreads();
    #pragma unroll
    for (int j = 0; j < 4; j++) {
        const int c = x0 + ty + (j << 3);
        out[(size_t)c * R + y0 + tx] = __float2half_rn(tile[tx][ty + (j << 3)]);
    }
}

// ---------------------------------------------------------------------------
// Reductions / elementwise
// ---------------------------------------------------------------------------
__inline__ __device__ float warpSum(float v) {
    #pragma unroll
    for (int o = 16; o > 0; o >>= 1) v += __shfl_xor_sync(0xffffffffu, v, o);
    return v;
}
__inline__ __device__ float warpMax(float v) {
    #pragma unroll
    for (int o = 16; o > 0; o >>= 1) v = fmaxf(v, __shfl_xor_sync(0xffffffffu, v, o));
    return v;
}

// LayerNorm over D=256: one WARP per row, float4 loads, shuffle-only reduce.
__global__ __launch_bounds__(256)
void ln_kernel(const float* __restrict__ x, const float* __restrict__ gamma,
               const float* __restrict__ beta, __half* __restrict__ out)
{
    const int warp = threadIdx.x >> 5, lane = threadIdx.x & 31;
    const long long row = (long long)blockIdx.x * 8 + warp;
    const float* xr = x + row * D_DIM + (lane << 3);

    const float4 v0 = *(const float4*)(xr);
    const float4 v1 = *(const float4*)(xr + 4);

    float s  = (v0.x + v0.y) + (v0.z + v0.w) + (v1.x + v1.y) + (v1.z + v1.w);
    float sq = v0.x*v0.x + v0.y*v0.y + v0.z*v0.z + v0.w*v0.w
             + v1.x*v1.x + v1.y*v1.y + v1.z*v1.z + v1.w*v1.w;
    s  = warpSum(s);
    sq = warpSum(sq);

    const float mu  = s * (1.0f / D_DIM);
    const float var = sq * (1.0f / D_DIM) - mu * mu;
    const float rs  = rsqrtf(var + 1e-5f);

    const float4 g0 = *(const float4*)(gamma + (lane << 3));
    const float4 g1 = *(const float4*)(gamma + (lane << 3) + 4);
    const float4 b0 = *(const float4*)(beta  + (lane << 3));
    const float4 b1 = *(const float4*)(beta  + (lane << 3) + 4);

    uint4 o;
    o.x = f2h2((v0.x - mu) * rs * g0.x + b0.x, (v0.y - mu) * rs * g0.y + b0.y);
    o.y = f2h2((v0.z - mu) * rs * g0.z + b0.z, (v0.w - mu) * rs * g0.w + b0.w);
    o.z = f2h2((v1.x - mu) * rs * g1.x + b1.x, (v1.y - mu) * rs * g1.y + b1.y);
    o.w = f2h2((v1.z - mu) * rs * g1.z + b1.z, (v1.w - mu) * rs * g1.w + b1.w);
    *(uint4*)(out + row * D_DIM + (lane << 3)) = o;
}

// Softmax over S=512 in-place (fp32) + fp16 copy
__global__ __launch_bounds__(128)
void softmax_kernel(float* __restrict__ p, __half* __restrict__ ph_all)
{
    const long long row = blockIdx.x;
    float* pr = p + row * S_LEN;
    __half* ph = ph_all + row * S_LEN;
    const int t = threadIdx.x;
    const int w = t >> 5, l = t & 31;

    float4 a = *(float4*)(pr + (t << 2));
    __shared__ float sh[4], sh2[4];

    float m = fmaxf(fmaxf(a.x, a.y), fmaxf(a.z, a.w));
    m = warpMax(m);
    if (l == 0) sh[w] = m;
    __syncthreads();
    m = fmaxf(fmaxf(sh[0], sh[1]), fmaxf(sh[2], sh[3]));

    a.x = __expf(a.x - m); a.y = __expf(a.y - m);
    a.z = __expf(a.z - m); a.w = __expf(a.w - m);
    float s = warpSum(a.x + a.y + a.z + a.w);
    if (l == 0) sh2[w] = s;
    __syncthreads();
    const float inv = 1.0f / (sh2[0] + sh2[1] + sh2[2] + sh2[3]);

    a.x *= inv; a.y *= inv; a.z *= inv; a.w *= inv;
    *(float4*)(pr + (t << 2)) = a;
    *(__half2*)(ph + (t << 2))     = __floats2half2_rn(a.x, a.y);
    *(__half2*)(ph + (t << 2) + 2) = __floats2half2_rn(a.z, a.w);
}

// Per-channel mean
__global__ __launch_bounds__(256)
void chmean_kernel(const float* __restrict__ h, float* __restrict__ y)
{
    const int c = blockIdx.x;
    const float4* hc = (const float4*)(h + (long long)c * S_LEN * D_DIM);
    float s = 0.f;
    for (int i = threadIdx.x; i < S_LEN * D_DIM / 4; i += 256) {
        float4 v = hc[i];
        s += (v.x + v.y) + (v.z + v.w);
    }
    __shared__ float sh[8];
    const int w = threadIdx.x >> 5, l = threadIdx.x & 31;
    s = warpSum(s);
    if (l == 0) sh[w] = s;
    __syncthreads();
    if (w == 0) {
        float v = (l < 8) ? sh[l] : 0.f;
        v = warpSum(v);
        if (l == 0) y[c] = v * (1.0f / (S_LEN * D_DIM));
    }
}

// SE gate
__global__ __launch_bounds__(256)
void se_kernel(const float* __restrict__ y,
               const float* __restrict__ W1, const float* __restrict__ b1,
               const float* __restrict__ W2, const float* __restrict__ b2,
               float* __restrict__ gate)
{
    __shared__ float ys[C_CH];
    __shared__ float hid[16];
    const int t = threadIdx.x;
    ys[t] = y[t];
    __syncthreads();
    if (t < 16) {
        float s = b1[t];
        #pragma unroll 8
        for (int c = 0; c < C_CH; c++) s += ys[c] * W1[c * 16 + t];
        hid[t] = fmaxf(s, 0.f);
    }
    __syncthreads();
    float s = b2[t];
    #pragma unroll
    for (int j = 0; j < 16; j++) s += hid[j] * W2[j * C_CH + t];
    gate[t] = 1.0f / (1.0f + __expf(-s));
}

// out = h * gate[c] + x
__global__ __launch_bounds__(256)
void final_kernel(float* __restrict__ out, const float* __restrict__ x,
                  const float* __restrict__ gate)
{
    const long long i4 = (long long)blockIdx.x * 256 + threadIdx.x;
    const int c = (int)(i4 >> 15);
    const float g = gate[c];
    float4 h = ((float4*)out)[i4];
    float4 xv = ((const float4*)x)[i4];
    h.x = h.x * g + xv.x;
    h.y = h.y * g + xv.y;
    h.z = h.z * g + xv.z;
    h.w = h.w * g + xv.w;
    ((float4*)out)[i4] = h;
}

// ---------------------------------------------------------------------------
// Launch
// ---------------------------------------------------------------------------
extern "C" void kernel_launch(void* const* d_in, const int* in_sizes, int n_in,
                              void* d_out, int out_size)
{
    const float* input = (const float*)d_in[0];
    const float* W_emb = (const float*)d_in[1];
    const float* b_emb = (const float*)d_in[2];
    const float* ln_g  = (const float*)d_in[3];
    const float* ln_b  = (const float*)d_in[4];
    const float* W1    = (const float*)d_in[5];
    const float* b1    = (const float*)d_in[6];
    const float* W2    = (const float*)d_in[7];
    const float* b2    = (const float*)d_in[8];
    const float* seW1  = (const float*)d_in[9];
    const float* seb1  = (const float*)d_in[10];
    const float* seW2  = (const float*)d_in[11];
    const float* seb2  = (const float*)d_in[12];

    float* out  = (float*)d_out;               // [C,S,D]
    float* attn = out + ELEMS;                 // [C,S,S] fp32 (output 1)

    float  *px, *py, *pg;
    __half *pn, *pnT, *po, *pffn, *pah, *pw1t, *pw2t;
    cudaGetSymbolAddress((void**)&px,   g_x);
    cudaGetSymbolAddress((void**)&pn,   g_n_h);
    cudaGetSymbolAddress((void**)&pnT,  g_nT_h);
    cudaGetSymbolAddress((void**)&po,   g_o_h);
    cudaGetSymbolAddress((void**)&pffn, g_ffn_h);
    cudaGetSymbolAddress((void**)&pah,  g_attn_h);
    cudaGetSymbolAddress((void**)&pw1t, g_w1t);
    cudaGetSymbolAddress((void**)&pw2t, g_w2t);
    cudaGetSymbolAddress((void**)&py,   g_y);
    cudaGetSymbolAddress((void**)&pg,   g_gate);

    const dim3 blk(256);
    const long long strideN = (long long)S_LEN * D_DIM;   // 131072
    const long long strideP = (long long)S_LEN * S_LEN;   // 262144

    // 0) weight transposes (fp32 -> fp16, transposed)
    transpose_f2h<<<dim3(D_FF / 32, D_DIM / 32), blk>>>(W1, pw1t, D_DIM, D_FF);
    transpose_f2h<<<dim3(D_DIM / 32, D_FF / 32), blk>>>(W2, pw2t, D_FF, D_DIM);

    // 1) x = input @ W_emb + b_emb
    mma_emb<<<dim3(D_DIM / 128, NROWS / 128), blk>>>(
        input, W_emb, b_emb, px, NROWS, D_DIM, D_IN);

    // 2) n = LayerNorm(x) -> fp16  (warp-per-row)
    ln_kernel<<<NROWS / 8, 256>>>(px, ln_g, ln_b, pn);

    // 3) nT per channel
    transpose_h<<<dim3(D_DIM / 32, S_LEN / 32, C_CH), blk>>>(pn, pnT, S_LEN, D_DIM);

    // 4) scores = (n @ n^T)/16 per channel -> attn fp32
    mma_nt<false, false, false><<<dim3(S_LEN / 128, S_LEN / 128, C_CH), blk>>>(
        pn, pn, nullptr, attn, S_LEN, S_LEN, D_DIM, 0.0625f,
        strideN, strideN, strideP);

    // 5) softmax in-place + fp16 copy
    softmax_kernel<<<C_CH * S_LEN, 128>>>(attn, pah);

    // 6) o = attn @ n per channel (NT with B = nT) -> fp16
    mma_nt<true, false, false><<<dim3(D_DIM / 128, S_LEN / 128, C_CH), blk>>>(
        pah, pnT, nullptr, po, S_LEN, D_DIM, S_LEN, 1.0f,
        strideP, strideN, strideN);

    // 7) h1 = relu(o @ W1 + b1) (NT with B = W1T) -> fp16
    mma_nt<true, true, true><<<dim3(D_FF / 128, NROWS / 128, 1), blk>>>(
        po, pw1t, b1, pffn, NROWS, D_FF, D_DIM, 1.0f, 0, 0, 0);

    // 8) h = h1 @ W2 + b2 (NT with B = W2T) -> fp32 out region
    mma_nt<false, false, true><<<dim3(D_DIM / 128, NROWS / 128, 1), blk>>>(
        pffn, pw2t, b2, out, NROWS, D_DIM, D_FF, 1.0f, 0, 0, 0);

    // 9) y[c] = mean(h[c])
    chmean_kernel<<<C_CH, 256>>>(out, py);

    // 10) SE gate
    se_kernel<<<1, 256>>>(py, seW1, seb1, seW2, seb2, pg);

    // 11) out = h * g[c] + x
    final_kernel<<<(unsigned)(ELEMS / 1024), 256>>>(out, px, pg);
}

// round 13
// speedup vs baseline: 4.2138x; 1.0188x over previous
#include <cuda_runtime.h>
#include <cuda_fp16.h>
#include <stdint.h>

// Problem constants
#define C_CH   256
#define S_LEN  512
#define D_DIM  256
#define D_IN   256
#define D_FF   1024
#define NROWS  (C_CH * S_LEN)              // 131072
#define ELEMS  ((long long)NROWS * D_DIM)  // 33,554,432

// ---------------------------------------------------------------------------
// Scratch (static; no allocation allowed)
// ---------------------------------------------------------------------------
__device__ float  g_x   [NROWS * D_DIM];                 // fp32 residual
__device__ __half g_in_h[NROWS * D_IN];                  // input fp16
__device__ __half g_n_h [NROWS * D_DIM];                 // layernorm out
__device__ __half g_nT_h[NROWS * D_DIM];                 // n transposed per channel
__device__ __half g_o_h [NROWS * D_DIM];                 // attention out
__device__ __half g_ffn_h[(size_t)NROWS * D_FF];         // FFN hidden
__device__ __half g_attn_h[(size_t)C_CH * S_LEN * S_LEN];// probs fp16
__device__ __half g_wembt[D_DIM * D_IN];                 // W_emb^T [256,256]
__device__ __half g_w1t [D_FF * D_DIM];                  // W1^T [1024,256]
__device__ __half g_w2t [D_DIM * D_FF];                  // W2^T [256,1024]
__device__ float  g_y   [C_CH];
__device__ float  g_gate[C_CH];

__device__ __forceinline__ uint32_t f2h2(float a, float b) {
    __half2 h = __floats2half2_rn(a, b);
    return *(uint32_t*)&h;
}

// cp.async helpers (L2-only path)
#define CP16(dst, src) asm volatile("cp.async.cg.shared.global [%0], [%1], 16;\n" :: "r"(dst), "l"(src))
#define CP_COMMIT()    asm volatile("cp.async.commit_group;\n")
#define CP_WAIT0()     asm volatile("cp.async.wait_group 0;\n")
#define CP_WAIT1()     asm volatile("cp.async.wait_group 1;\n")

__device__ __forceinline__ void ldsmx4(uint32_t& r0, uint32_t& r1,
                                       uint32_t& r2, uint32_t& r3, uint32_t a) {
    asm volatile("ldmatrix.sync.aligned.m8n8.x4.shared.b16 {%0,%1,%2,%3}, [%4];"
                 : "=r"(r0), "=r"(r1), "=r"(r2), "=r"(r3) : "r"(a));
}
__device__ __forceinline__ void ldsmx2(uint32_t& r0, uint32_t& r1, uint32_t a) {
    asm volatile("ldmatrix.sync.aligned.m8n8.x2.shared.b16 {%0,%1}, [%2];"
                 : "=r"(r0), "=r"(r1) : "r"(a));
}

// ===========================================================================
// Unified NT fp16 GEMM:  C = alpha * A @ B^T [+bias] [relu]
//   A: [M,K] half row-major,  B: [N,K] half row-major, batch via blockIdx.z.
//   Tile 128x128x32, 256 threads (8 warps 2x4), warp tile 64x32.
//   3-stage cp.async ring (dynamic smem, 61440B), wait_group 1 steady-state.
//   Stage layout: A 128 rows x 20 u32 (80B stride) at +0, B same at +10240B.
//   80B stride is conflict-free for cp.async stores and ldmatrix reads (R12-proven).
// ===========================================================================
#define STAGE_BYTES 20480
#define B_OFF_BYTES 10240

template<bool OUT_HALF, bool RELU, bool HAS_BIAS>
__global__ __launch_bounds__(256)
void mma_nt(const __half* __restrict__ Aall, const __half* __restrict__ Ball,
            const float* __restrict__ bias, void* __restrict__ Call,
            int M, int N, int K, float alpha,
            long long sA, long long sB, long long sC)
{
    extern __shared__ uint32_t smem_dyn[];
    const uint32_t smemBase = (uint32_t)__cvta_generic_to_shared(smem_dyn);

    const __half* A = Aall + (long long)blockIdx.z * sA;
    const __half* B = Ball + (long long)blockIdx.z * sB;

    const int t     = threadIdx.x;
    const int lane  = t & 31;
    const int warp  = t >> 5;
    const int warpM = warp >> 2;   // 0..1
    const int warpN = warp & 3;    // 0..3
    const int g8    = lane >> 2;   // 0..7
    const int tig   = lane & 3;    // 0..3

    // global loader: thread t -> row t>>1, 32B chunk (t&1)
    const int lRow = t >> 1;
    const __half* aSrc = A + (size_t)((blockIdx.y << 7) + lRow) * K + ((t & 1) << 4);
    const __half* bSrc = B + (size_t)((blockIdx.x << 7) + lRow) * K + ((t & 1) << 4);

    // per-thread smem store byte offsets within a stage
    const uint32_t stOffA = (uint32_t)(lRow * 80 + ((t & 1) << 5));
    const uint32_t stOffB = stOffA + B_OFF_BYTES;

    // ldmatrix lane byte offsets within a stage
    const uint32_t aLdOff = (uint32_t)(((warpM << 6) + (lane & 15)) * 80 + ((lane >> 4) << 4));
    const uint32_t bLdOff = (uint32_t)(B_OFF_BYTES + ((warpN << 5) + (lane & 7)) * 80
                                       + (((lane >> 3) & 1) << 4));

    float acc[4][4][4];
    #pragma unroll
    for (int i = 0; i < 4; i++)
        #pragma unroll
        for (int j = 0; j < 4; j++)
            #pragma unroll
            for (int r = 0; r < 4; r++) acc[i][j][r] = 0.0f;

    const int nslabs = K >> 5;

    auto issue = [&](int slab, int stage) {
        const uint32_t base = smemBase + (uint32_t)stage * STAGE_BYTES;
        const __half* as = aSrc + (slab << 5);
        const __half* bs = bSrc + (slab << 5);
        CP16(base + stOffA,      as);
        CP16(base + stOffA + 16, as + 8);
        CP16(base + stOffB,      bs);
        CP16(base + stOffB + 16, bs + 8);
        CP_COMMIT();
    };

    // prologue: 2 slabs in flight
    issue(0, 0);
    if (nslabs > 1) issue(1, 1);

    int stage = 0;
    for (int i = 0; i < nslabs; i++) {
        if (i + 1 < nslabs) CP_WAIT1(); else CP_WAIT0();
        __syncthreads();

        if (i + 2 < nslabs) {
            int ns = stage + 2; if (ns >= 3) ns -= 3;
            issue(i + 2, ns);
        }

        const uint32_t aLd = smemBase + (uint32_t)stage * STAGE_BYTES + aLdOff;
        const uint32_t bLd = smemBase + (uint32_t)stage * STAGE_BYTES + bLdOff;

        #pragma unroll
        for (int ks = 0; ks < 2; ks++) {
            uint32_t af[4][4], bf[4][2];
            #pragma unroll
            for (int mt = 0; mt < 4; mt++)
                ldsmx4(af[mt][0], af[mt][1], af[mt][2], af[mt][3],
                       aLd + mt * (16 * 80) + ks * 32);
            #pragma unroll
            for (int nt = 0; nt < 4; nt++)
                ldsmx2(bf[nt][0], bf[nt][1],
                       bLd + nt * (8 * 80) + ks * 32);
            #pragma unroll
            for (int mt = 0; mt < 4; mt++)
                #pragma unroll
                for (int nt = 0; nt < 4; nt++)
                    asm volatile(
                        "mma.sync.aligned.m16n8k16.row.col.f32.f16.f16.f32 "
                        "{%0,%1,%2,%3}, {%4,%5,%6,%7}, {%8,%9}, {%0,%1,%2,%3};"
                        : "+f"(acc[mt][nt][0]), "+f"(acc[mt][nt][1]),
                          "+f"(acc[mt][nt][2]), "+f"(acc[mt][nt][3])
                        : "r"(af[mt][0]), "r"(af[mt][1]),
                          "r"(af[mt][2]), "r"(af[mt][3]),
                          "r"(bf[nt][0]), "r"(bf[nt][1]));
        }
        if (++stage == 3) stage = 0;
    }

    // ---- epilogue ----
    const int rowB = (blockIdx.y << 7) + (warpM << 6) + g8;
    const int colB = (blockIdx.x << 7) + (warpN << 5) + (tig << 1);

    #pragma unroll
    for (int nt = 0; nt < 4; nt++) {
        const int col = colB + (nt << 3);
        float b0 = 0.f, b1 = 0.f;
        if (HAS_BIAS) { b0 = bias[col]; b1 = bias[col + 1]; }
        #pragma unroll
        for (int mt = 0; mt < 4; mt++) {
            float v0 = acc[mt][nt][0] * alpha + b0;
            float v1 = acc[mt][nt][1] * alpha + b1;
            float v2 = acc[mt][nt][2] * alpha + b0;
            float v3 = acc[mt][nt][3] * alpha + b1;
            if (RELU) {
                v0 = fmaxf(v0, 0.f); v1 = fmaxf(v1, 0.f);
                v2 = fmaxf(v2, 0.f); v3 = fmaxf(v3, 0.f);
            }
            const int r0 = rowB + (mt << 4);
            if (OUT_HALF) {
                __half* Cp = (__half*)Call + (long long)blockIdx.z * sC;
                *(__half2*)(Cp + (size_t)r0 * N + col)       = __floats2half2_rn(v0, v1);
                *(__half2*)(Cp + (size_t)(r0 + 8) * N + col) = __floats2half2_rn(v2, v3);
            } else {
                float* Cp = (float*)Call + (long long)blockIdx.z * sC;
                *(float2*)(Cp + (size_t)r0 * N + col)       = make_float2(v0, v1);
                *(float2*)(Cp + (size_t)(r0 + 8) * N + col) = make_float2(v2, v3);
            }
        }
    }
}

// ---------------------------------------------------------------------------
// fp32 -> fp16 convert (8 elems/thread)
// ---------------------------------------------------------------------------
__global__ __launch_bounds__(256)
void f2h_kernel(const float* __restrict__ in, __half* __restrict__ out)
{
    const long long i = ((long long)blockIdx.x * 256 + threadIdx.x) << 3;
    const float4 v0 = *(const float4*)(in + i);
    const float4 v1 = *(const float4*)(in + i + 4);
    uint4 o;
    o.x = f2h2(v0.x, v0.y);
    o.y = f2h2(v0.z, v0.w);
    o.z = f2h2(v1.x, v1.y);
    o.w = f2h2(v1.z, v1.w);
    *(uint4*)(out + i) = o;
}

// ---------------------------------------------------------------------------
// Transposes
// ---------------------------------------------------------------------------
__global__ __launch_bounds__(256)
void transpose_h(const __half* __restrict__ in, __half* __restrict__ out,
                 int R, int C)
{
    __shared__ __half tile[32][33];
    const size_t base = (size_t)blockIdx.z * R * C;
    const int x0 = blockIdx.x << 5, y0 = blockIdx.y << 5;
    const int tx = threadIdx.x & 31, ty = threadIdx.x >> 5;
    #pragma unroll
    for (int j = 0; j < 4; j++) {
        const int r = y0 + ty + (j << 3);
        tile[ty + (j << 3)][tx] = in[base + (size_t)r * C + x0 + tx];
    }
    __syncthreads();
    #pragma unroll
    for (int j = 0; j < 4; j++) {
        const int c = x0 + ty + (j << 3);
        out[base + (size_t)c * R + y0 + tx] = tile[tx][ty + (j << 3)];
    }
}

__global__ __launch_bounds__(256)
void transpose_f2h(const float* __restrict__ in, __half* __restrict__ out,
                   int R, int C)
{
    __shared__ float tile[32][33];
    const int x0 = blockIdx.x << 5, y0 = blockIdx.y << 5;
    const int tx = threadIdx.x & 31, ty = threadIdx.x >> 5;
    #pragma unroll
    for (int j = 0; j < 4; j++) {
        const int r = y0 + ty + (j << 3);
        tile[ty + (j << 3)][tx] = in[(size_t)r * C + x0 + tx];
    }
    __syncthreads();
    #pragma unroll
    for (int j = 0; j < 4; j++) {
        const int c = x0 + ty + (j << 3);
        out[(size_t)c * R + y0 + tx] = __float2half_rn(tile[tx][ty + (j << 3)]);
    }
}

// ---------------------------------------------------------------------------
// Reductions / elementwise
// ---------------------------------------------------------------------------
__inline__ __device__ float warpSum(float v) {
    #pragma unroll
    for (int o = 16; o > 0; o >>= 1) v += __shfl_xor_sync(0xffffffffu, v, o);
    return v;
}
__inline__ __device__ float warpMax(float v) {
    #pragma unroll
    for (int o = 16; o > 0; o >>= 1) v = fmaxf(v, __shfl_xor_sync(0xffffffffu, v, o));
    return v;
}

// LayerNorm over D=256: one WARP per row
__global__ __launch_bounds__(256)
void ln_kernel(const float* __restrict__ x, const float* __restrict__ gamma,
               const float* __restrict__ beta, __half* __restrict__ out)
{
    const int warp = threadIdx.x >> 5, lane = threadIdx.x & 31;
    const long long row = (long long)blockIdx.x * 8 + warp;
    const float* xr = x + row * D_DIM + (lane << 3);

    const float4 v0 = *(const float4*)(xr);
    const float4 v1 = *(const float4*)(xr + 4);

    float s  = (v0.x + v0.y) + (v0.z + v0.w) + (v1.x + v1.y) + (v1.z + v1.w);
    float sq = v0.x*v0.x + v0.y*v0.y + v0.z*v0.z + v0.w*v0.w
             + v1.x*v1.x + v1.y*v1.y + v1.z*v1.z + v1.w*v1.w;
    s  = warpSum(s);
    sq = warpSum(sq);

    const float mu  = s * (1.0f / D_DIM);
    const float var = sq * (1.0f / D_DIM) - mu * mu;
    const float rs  = rsqrtf(var + 1e-5f);

    const float4 g0 = *(const float4*)(gamma + (lane << 3));
    const float4 g1 = *(const float4*)(gamma + (lane << 3) + 4);
    const float4 b0 = *(const float4*)(beta  + (lane << 3));
    const float4 b1 = *(const float4*)(beta  + (lane << 3) + 4);

    uint4 o;
    o.x = f2h2((v0.x - mu) * rs * g0.x + b0.x, (v0.y - mu) * rs * g0.y + b0.y);
    o.y = f2h2((v0.z - mu) * rs * g0.z + b0.z, (v0.w - mu) * rs * g0.w + b0.w);
    o.z = f2h2((v1.x - mu) * rs * g1.x + b1.x, (v1.y - mu) * rs * g1.y + b1.y);
    o.w = f2h2((v1.z - mu) * rs * g1.z + b1.z, (v1.w - mu) * rs * g1.w + b1.w);
    *(uint4*)(out + row * D_DIM + (lane << 3)) = o;
}

// Softmax over S=512 in-place (fp32) + fp16 copy
__global__ __launch_bounds__(128)
void softmax_kernel(float* __restrict__ p, __half* __restrict__ ph_all)
{
    const long long row = blockIdx.x;
    float* pr = p + row * S_LEN;
    __half* ph = ph_all + row * S_LEN;
    const int t = threadIdx.x;
    const int w = t >> 5, l = t & 31;

    float4 a = *(float4*)(pr + (t << 2));
    __shared__ float sh[4], sh2[4];

    float m = fmaxf(fmaxf(a.x, a.y), fmaxf(a.z, a.w));
    m = warpMax(m);
    if (l == 0) sh[w] = m;
    __syncthreads();
    m = fmaxf(fmaxf(sh[0], sh[1]), fmaxf(sh[2], sh[3]));

    a.x = __expf(a.x - m); a.y = __expf(a.y - m);
    a.z = __expf(a.z - m); a.w = __expf(a.w - m);
    float s = warpSum(a.x + a.y + a.z + a.w);
    if (l == 0) sh2[w] = s;
    __syncthreads();
    const float inv = 1.0f / (sh2[0] + sh2[1] + sh2[2] + sh2[3]);

    a.x *= inv; a.y *= inv; a.z *= inv; a.w *= inv;
    *(float4*)(pr + (t << 2)) = a;
    *(__half2*)(ph + (t << 2))     = __floats2half2_rn(a.x, a.y);
    *(__half2*)(ph + (t << 2) + 2) = __floats2half2_rn(a.z, a.w);
}

// Per-channel mean
__global__ __launch_bounds__(256)
void chmean_kernel(const float* __restrict__ h, float* __restrict__ y)
{
    const int c = blockIdx.x;
    const float4* hc = (const float4*)(h + (long long)c * S_LEN * D_DIM);
    float s = 0.f;
    for (int i = threadIdx.x; i < S_LEN * D_DIM / 4; i += 256) {
        float4 v = hc[i];
        s += (v.x + v.y) + (v.z + v.w);
    }
    __shared__ float sh[8];
    const int w = threadIdx.x >> 5, l = threadIdx.x & 31;
    s = warpSum(s);
    if (l == 0) sh[w] = s;
    __syncthreads();
    if (w == 0) {
        float v = (l < 8) ? sh[l] : 0.f;
        v = warpSum(v);
        if (l == 0) y[c] = v * (1.0f / (S_LEN * D_DIM));
    }
}

// SE gate
__global__ __launch_bounds__(256)
void se_kernel(const float* __restrict__ y,
               const float* __restrict__ W1, const float* __restrict__ b1,
               const float* __restrict__ W2, const float* __restrict__ b2,
               float* __restrict__ gate)
{
    __shared__ float ys[C_CH];
    __shared__ float hid[16];
    const int t = threadIdx.x;
    ys[t] = y[t];
    __syncthreads();
    if (t < 16) {
        float s = b1[t];
        #pragma unroll 8
        for (int c = 0; c < C_CH; c++) s += ys[c] * W1[c * 16 + t];
        hid[t] = fmaxf(s, 0.f);
    }
    __syncthreads();
    float s = b2[t];
    #pragma unroll
    for (int j = 0; j < 16; j++) s += hid[j] * W2[j * C_CH + t];
    gate[t] = 1.0f / (1.0f + __expf(-s));
}

// out = h * gate[c] + x
__global__ __launch_bounds__(256)
void final_kernel(float* __restrict__ out, const float* __restrict__ x,
                  const float* __restrict__ gate)
{
    const long long i4 = (long long)blockIdx.x * 256 + threadIdx.x;
    const int c = (int)(i4 >> 15);
    const float g = gate[c];
    float4 h = ((float4*)out)[i4];
    float4 xv = ((const float4*)x)[i4];
    h.x = h.x * g + xv.x;
    h.y = h.y * g + xv.y;
    h.z = h.z * g + xv.z;
    h.w = h.w * g + xv.w;
    ((float4*)out)[i4] = h;
}

// ---------------------------------------------------------------------------
// Launch
// ---------------------------------------------------------------------------
extern "C" void kernel_launch(void* const* d_in, const int* in_sizes, int n_in,
                              void* d_out, int out_size)
{
    const float* input = (const float*)d_in[0];
    const float* W_emb = (const float*)d_in[1];
    const float* b_emb = (const float*)d_in[2];
    const float* ln_g  = (const float*)d_in[3];
    const float* ln_b  = (const float*)d_in[4];
    const float* W1    = (const float*)d_in[5];
    const float* b1    = (const float*)d_in[6];
    const float* W2    = (const float*)d_in[7];
    const float* b2    = (const float*)d_in[8];
    const float* seW1  = (const float*)d_in[9];
    const float* seb1  = (const float*)d_in[10];
    const float* seW2  = (const float*)d_in[11];
    const float* seb2  = (const float*)d_in[12];

    float* out  = (float*)d_out;               // [C,S,D]
    float* attn = out + ELEMS;                 // [C,S,S] fp32 (output 1)

    float  *px, *py, *pg;
    __half *pih, *pn, *pnT, *po, *pffn, *pah, *pwet, *pw1t, *pw2t;
    cudaGetSymbolAddress((void**)&px,   g_x);
    cudaGetSymbolAddress((void**)&pih,  g_in_h);
    cudaGetSymbolAddress((void**)&pn,   g_n_h);
    cudaGetSymbolAddress((void**)&pnT,  g_nT_h);
    cudaGetSymbolAddress((void**)&po,   g_o_h);
    cudaGetSymbolAddress((void**)&pffn, g_ffn_h);
    cudaGetSymbolAddress((void**)&pah,  g_attn_h);
    cudaGetSymbolAddress((void**)&pwet, g_wembt);
    cudaGetSymbolAddress((void**)&pw1t, g_w1t);
    cudaGetSymbolAddress((void**)&pw2t, g_w2t);
    cudaGetSymbolAddress((void**)&py,   g_y);
    cudaGetSymbolAddress((void**)&pg,   g_gate);

    // raise dynamic smem limit for the GEMM instantiations (idempotent)
    const int DYN = 3 * STAGE_BYTES;   // 61440
    cudaFuncSetAttribute(mma_nt<false, false, false>, cudaFuncAttributeMaxDynamicSharedMemorySize, DYN);
    cudaFuncSetAttribute(mma_nt<true,  false, false>, cudaFuncAttributeMaxDynamicSharedMemorySize, DYN);
    cudaFuncSetAttribute(mma_nt<true,  true,  true >, cudaFuncAttributeMaxDynamicSharedMemorySize, DYN);
    cudaFuncSetAttribute(mma_nt<false, false, true >, cudaFuncAttributeMaxDynamicSharedMemorySize, DYN);

    const dim3 blk(256);
    const long long strideN = (long long)S_LEN * D_DIM;   // 131072
    const long long strideP = (long long)S_LEN * S_LEN;   // 262144

    // 0) weight transposes (fp32 -> fp16, transposed) + input convert
    transpose_f2h<<<dim3(D_DIM / 32, D_IN / 32), blk>>>(W_emb, pwet, D_IN, D_DIM);
    transpose_f2h<<<dim3(D_FF / 32, D_DIM / 32), blk>>>(W1, pw1t, D_DIM, D_FF);
    transpose_f2h<<<dim3(D_DIM / 32, D_FF / 32), blk>>>(W2, pw2t, D_FF, D_DIM);
    f2h_kernel<<<(unsigned)(ELEMS / 2048), blk>>>(input, pih);

    // 1) x = input @ W_emb + b_emb  (NT, B = W_emb^T) -> fp32
    mma_nt<false, false, true><<<dim3(D_DIM / 128, NROWS / 128, 1), blk, DYN>>>(
        pih, pwet, b_emb, px, NROWS, D_DIM, D_IN, 1.0f, 0, 0, 0);

    // 2) n = LayerNorm(x) -> fp16
    ln_kernel<<<NROWS / 8, 256>>>(px, ln_g, ln_b, pn);

    // 3) nT per channel
    transpose_h<<<dim3(D_DIM / 32, S_LEN / 32, C_CH), blk>>>(pn, pnT, S_LEN, D_DIM);

    // 4) scores = (n @ n^T)/16 per channel -> attn fp32
    mma_nt<false, false, false><<<dim3(S_LEN / 128, S_LEN / 128, C_CH), blk, DYN>>>(
        pn, pn, nullptr, attn, S_LEN, S_LEN, D_DIM, 0.0625f,
        strideN, strideN, strideP);

    // 5) softmax in-place + fp16 copy
    softmax_kernel<<<C_CH * S_LEN, 128>>>(attn, pah);

    // 6) o = attn @ n per channel (NT with B = nT) -> fp16
    mma_nt<true, false, false><<<dim3(D_DIM / 128, S_LEN / 128, C_CH), blk, DYN>>>(
        pah, pnT, nullptr, po, S_LEN, D_DIM, S_LEN, 1.0f,
        strideP, strideN, strideN);

    // 7) h1 = relu(o @ W1 + b1) (NT with B = W1T) -> fp16
    mma_nt<true, true, true><<<dim3(D_FF / 128, NROWS / 128, 1), blk, DYN>>>(
        po, pw1t, b1, pffn, NROWS, D_FF, D_DIM, 1.0f, 0, 0, 0);

    // 8) h = h1 @ W2 + b2 (NT with B = W2T) -> fp32 out region
    mma_nt<false, false, true><<<dim3(D_DIM / 128, NROWS / 128, 1), blk, DYN>>>(
        pffn, pw2t, b2, out, NROWS, D_DIM, D_FF, 1.0f, 0, 0, 0);

    // 9) y[c] = mean(h[c])
    chmean_kernel<<<C_CH, 256>>>(out, py);

    // 10) SE gate
    se_kernel<<<1, 256>>>(py, seW1, seb1, seW2, seb2, pg);

    // 11) out = h * g[c] + x
    final_kernel<<<(unsigned)(ELEMS / 1024), 256>>>(out, px, pg);
}